// round 2
// baseline (speedup 1.0000x reference)
#include <cuda_runtime.h>

#define BB 2048
#define NN 64
#define EPG 512
#define TOTAL_N (BB*NN)      // 131072
#define TOTAL_E (BB*EPG)     // 1048576
#define DN 16
#define DE 64
#define DU 32
#define DUE 64
#define HID 512
#define HID2 256
#define SDIM (NN*DE + DUE)   // 4160
#define MASK_WORDS (TOTAL_N*DE/32)   // 262144

// ---------------- scratch (no allocs allowed) ----------------
__device__ float g_states[BB*SDIM];   // 34 MB
__device__ float g_h1[BB*HID];
__device__ float g_h2[BB*HID2];
__device__ float g_logits[BB*NN];
__device__ unsigned int g_mask[MASK_WORDS];

// ---------------- threefry2x32 (JAX, key = PRNGKey(42) = {0,42}) ----------------
__device__ __forceinline__ unsigned int rotl32(unsigned int v, int d) {
    return __funnelshift_l(v, v, d);
}

// Full 20-round Threefry-2x32. JAX partitionable 32-bit path returns out0 ^ out1.
__device__ __forceinline__ unsigned int threefry_xor(unsigned int x0, unsigned int x1) {
    const unsigned int K0 = 0u, K1 = 42u;
    const unsigned int K2c = 0x1BD11BDAu ^ K0 ^ K1;
#define TF_ROUND(r) { x0 += x1; x1 = rotl32(x1, r); x1 ^= x0; }
    x0 += K0; x1 += K1;
    TF_ROUND(13) TF_ROUND(15) TF_ROUND(26) TF_ROUND(6)
    x0 += K1;  x1 += K2c + 1u;
    TF_ROUND(17) TF_ROUND(29) TF_ROUND(16) TF_ROUND(24)
    x0 += K2c; x1 += K0 + 2u;
    TF_ROUND(13) TF_ROUND(15) TF_ROUND(26) TF_ROUND(6)
    x0 += K0;  x1 += K1 + 3u;
    TF_ROUND(17) TF_ROUND(29) TF_ROUND(16) TF_ROUND(24)
    x0 += K1;  x1 += K2c + 4u;
    TF_ROUND(13) TF_ROUND(15) TF_ROUND(26) TF_ROUND(6)
    x0 += K2c; x1 += K0 + 5u;
#undef TF_ROUND
    return x0 ^ x1;
}

// Partitionable scheme, 32-bit: element i -> threefry(key, (hi(i)=0, lo(i)=i)),
// bits = out0 ^ out1.  keep <=> uniform < 0.5 <=> MSB(bits) == 0.
__global__ void mask_kernel() {
    unsigned int i = blockIdx.x * blockDim.x + threadIdx.x;
    unsigned int bits = threefry_xor(0u, i);
    int keep = (bits >> 31) == 0u;
    unsigned int bal = __ballot_sync(0xffffffffu, keep);
    if ((threadIdx.x & 31) == 0) g_mask[i >> 5] = bal;
}

// ---------------- per-graph GNN kernel ----------------
// block = one graph (2048 blocks, 256 threads)
__global__ __launch_bounds__(256) void graph_kernel(
    const float* __restrict__ x, const float* __restrict__ edge_attr,
    const float* __restrict__ user_s,
    const float* __restrict__ W_msg, const float* __restrict__ b_msg,
    const float* __restrict__ W_edge, const float* __restrict__ b_edge,
    const float* __restrict__ W_self, const float* __restrict__ b_self,
    const float* __restrict__ W1, const float* __restrict__ b1,
    const int* __restrict__ edge_index)
{
    __shared__ float sWm[DN][DE];        // 4 KB
    __shared__ float sWs[DN][DE];        // 4 KB
    __shared__ float sWe[2][DE];         // 0.5 KB
    __shared__ float sbme[DE];           // b_msg + b_edge
    __shared__ float sbs[DE];            // b_self
    __shared__ float sx[NN][DN];         // 4 KB
    __shared__ float sxm[NN][DE + 1];    // x@W_msg, padded (16.25 KB)
    __shared__ float sA[NN][NN + 1];     // adjacency counts, padded (16.25 KB)
    __shared__ float sea[NN][2];         // edge_attr aggregated at dst

    const int b = blockIdx.x;
    const int t = threadIdx.x;

    for (int i = t; i < DN * DE; i += 256) {
        sWm[i / DE][i % DE] = W_msg[i];
        sWs[i / DE][i % DE] = W_self[i];
    }
    for (int i = t; i < 2 * DE; i += 256) sWe[i / DE][i % DE] = W_edge[i];
    if (t < DE) { sbme[t] = b_msg[t] + b_edge[t]; sbs[t] = b_self[t]; }
    for (int i = t; i < NN * DN; i += 256) sx[i / DN][i % DN] = x[b * NN * DN + i];
    for (int i = t; i < NN * (NN + 1); i += 256) (&sA[0][0])[i] = 0.f;
    if (t < NN) { sea[t][0] = 0.f; sea[t][1] = 0.f; }
    __syncthreads();

    const int n = t >> 2;            // node 0..63
    const int d0 = (t & 3) * 16;     // dim chunk

    // xm = x @ W_msg
    {
        float acc[16];
        #pragma unroll
        for (int j = 0; j < 16; j++) acc[j] = 0.f;
        #pragma unroll
        for (int k = 0; k < DN; k++) {
            float xv = sx[n][k];
            #pragma unroll
            for (int j = 0; j < 16; j++) acc[j] += xv * sWm[k][d0 + j];
        }
        #pragma unroll
        for (int j = 0; j < 16; j++) sxm[n][d0 + j] = acc[j];
    }

    // edges: build adjacency counts + aggregated edge attrs (3 shared atomics/edge)
    {
        const int ebase = b * EPG;
        for (int e = t; e < EPG; e += 256) {
            int src = edge_index[ebase + e];
            int dst = edge_index[TOTAL_E + ebase + e];
            int sl = src - b * NN;
            int dl = dst - b * NN;
            atomicAdd(&sA[dl][sl], 1.f);
            float ea0 = edge_attr[(ebase + e) * 2];
            float ea1 = edge_attr[(ebase + e) * 2 + 1];
            atomicAdd(&sea[dl][0], ea0);
            atomicAdd(&sea[dl][1], ea1);
        }
    }
    __syncthreads();

    // combine: agg = A@xm + ea@W_edge + deg*(b_msg+b_edge); node = relu(agg + x@W_self + b_self)
    {
        float acc[16];
        #pragma unroll
        for (int j = 0; j < 16; j++) acc[j] = sbs[d0 + j];
        #pragma unroll
        for (int k = 0; k < DN; k++) {
            float xv = sx[n][k];
            #pragma unroll
            for (int j = 0; j < 16; j++) acc[j] += xv * sWs[k][d0 + j];
        }
        float deg = 0.f;
        for (int u = 0; u < NN; u++) {
            float a = sA[n][u];
            deg += a;
            if (a != 0.f) {
                #pragma unroll
                for (int j = 0; j < 16; j++) acc[j] += a * sxm[u][d0 + j];
            }
        }
        float e0 = sea[n][0], e1 = sea[n][1];
        #pragma unroll
        for (int j = 0; j < 16; j++) {
            int d = d0 + j;
            float v = acc[j] + e0 * sWe[0][d] + e1 * sWe[1][d] + deg * sbme[d];
            v = (v > 0.f) ? v * 2.f : 0.f;                 // relu then dropout scale
            unsigned int idx = (unsigned int)(b * NN + n) * DE + d;
            unsigned int w = g_mask[idx >> 5];
            if (!((w >> (idx & 31)) & 1u)) v = 0.f;        // dropout mask
            g_states[b * SDIM + n * DE + d] = v;
        }
    }

    // user embedding: relu(user_s @ W1 + b1) -> states[b][4096:4160]
    if (t < DUE) {
        float acc = b1[t];
        #pragma unroll
        for (int k = 0; k < DU; k++) acc += user_s[b * DU + k] * W1[k * DUE + t];
        g_states[b * SDIM + NN * DE + t] = fmaxf(acc, 0.f);
    }
}

// ---------------- generic tiled fp32 SGEMM: C = act(A[M,K] @ Bw[K,N] + bias) ----------------
template <bool RELU>
__global__ __launch_bounds__(256) void sgemm_bias(
    const float* __restrict__ A, const float* __restrict__ Bw,
    const float* __restrict__ bias, float* __restrict__ C,
    int M, int Nn, int K)
{
    __shared__ float As[16][68];   // [k][m], padded
    __shared__ float Bs[16][68];   // [k][n], padded

    const int t = threadIdx.x;
    const int tx = t & 15, ty = t >> 4;
    const int n0 = blockIdx.x * 64, m0 = blockIdx.y * 64;

    const int am = t >> 2, ak = (t & 3) * 4;   // A-load: row am, k = ak..ak+3
    const int bk = t >> 4, bn = (t & 15) * 4;  // B-load: k = bk, col bn..bn+3

    float c00=0,c01=0,c02=0,c03=0, c10=0,c11=0,c12=0,c13=0;
    float c20=0,c21=0,c22=0,c23=0, c30=0,c31=0,c32=0,c33=0;

    for (int k0 = 0; k0 < K; k0 += 16) {
        float4 av = *(const float4*)(A + (size_t)(m0 + am) * K + k0 + ak);
        float4 bv = *(const float4*)(Bw + (size_t)(k0 + bk) * Nn + n0 + bn);
        As[ak + 0][am] = av.x; As[ak + 1][am] = av.y;
        As[ak + 2][am] = av.z; As[ak + 3][am] = av.w;
        *(float4*)(&Bs[bk][bn]) = bv;
        __syncthreads();
        #pragma unroll
        for (int k = 0; k < 16; k++) {
            float4 a = *(const float4*)(&As[k][ty * 4]);
            float4 b = *(const float4*)(&Bs[k][tx * 4]);
            c00 += a.x*b.x; c01 += a.x*b.y; c02 += a.x*b.z; c03 += a.x*b.w;
            c10 += a.y*b.x; c11 += a.y*b.y; c12 += a.y*b.z; c13 += a.y*b.w;
            c20 += a.z*b.x; c21 += a.z*b.y; c22 += a.z*b.z; c23 += a.z*b.w;
            c30 += a.w*b.x; c31 += a.w*b.y; c32 += a.w*b.z; c33 += a.w*b.w;
        }
        __syncthreads();
    }

    float cr[4][4] = {{c00,c01,c02,c03},{c10,c11,c12,c13},{c20,c21,c22,c23},{c30,c31,c32,c33}};
    #pragma unroll
    for (int i = 0; i < 4; i++) {
        int m = m0 + ty * 4 + i;
        #pragma unroll
        for (int j = 0; j < 4; j++) {
            int nc = n0 + tx * 4 + j;
            float v = cr[i][j] + bias[nc];
            if (RELU) v = fmaxf(v, 0.f);
            C[(size_t)m * Nn + nc] = v;
        }
    }
}

// ---------------- softmax over the BATCH axis (axis 0 of [B, N]) ----------------
__global__ __launch_bounds__(256) void softmax_kernel(
    const float* __restrict__ logits, float* __restrict__ out)
{
    const int ncol = blockIdx.x;   // 0..63
    const int t = threadIdx.x;
    __shared__ float red[256];

    float mx = -1e30f;
    for (int bi = t; bi < BB; bi += 256) mx = fmaxf(mx, logits[bi * NN + ncol]);
    red[t] = mx; __syncthreads();
    for (int s = 128; s > 0; s >>= 1) { if (t < s) red[t] = fmaxf(red[t], red[t + s]); __syncthreads(); }
    mx = red[0]; __syncthreads();

    float sum = 0.f;
    for (int bi = t; bi < BB; bi += 256) sum += expf(logits[bi * NN + ncol] - mx);
    red[t] = sum; __syncthreads();
    for (int s = 128; s > 0; s >>= 1) { if (t < s) red[t] += red[t + s]; __syncthreads(); }
    float inv = 1.f / red[0];

    for (int bi = t; bi < BB; bi += 256)
        out[bi * NN + ncol] = expf(logits[bi * NN + ncol] - mx) * inv;
}

// ---------------- launch ----------------
extern "C" void kernel_launch(void* const* d_in, const int* in_sizes, int n_in,
                              void* d_out, int out_size)
{
    const float* x         = (const float*)d_in[0];
    const float* edge_attr = (const float*)d_in[1];
    const float* user_s    = (const float*)d_in[2];
    const float* W_msg     = (const float*)d_in[3];
    const float* b_msg     = (const float*)d_in[4];
    const float* W_edge    = (const float*)d_in[5];
    const float* b_edge    = (const float*)d_in[6];
    const float* W_self    = (const float*)d_in[7];
    const float* b_self    = (const float*)d_in[8];
    const float* W1        = (const float*)d_in[9];
    const float* b1        = (const float*)d_in[10];
    const float* W2        = (const float*)d_in[11];
    const float* b2        = (const float*)d_in[12];
    const float* W3        = (const float*)d_in[13];
    const float* b3        = (const float*)d_in[14];
    const float* W4        = (const float*)d_in[15];
    const float* b4        = (const float*)d_in[16];
    const int*   edge_index = (const int*)d_in[17];
    float* out = (float*)d_out;

    float *states, *h1, *h2, *logits;
    cudaGetSymbolAddress((void**)&states, g_states);
    cudaGetSymbolAddress((void**)&h1, g_h1);
    cudaGetSymbolAddress((void**)&h2, g_h2);
    cudaGetSymbolAddress((void**)&logits, g_logits);

    mask_kernel<<<TOTAL_N * DE / 256, 256>>>();
    graph_kernel<<<BB, 256>>>(x, edge_attr, user_s, W_msg, b_msg, W_edge, b_edge,
                              W_self, b_self, W1, b1, edge_index);
    sgemm_bias<true ><<<dim3(HID  / 64, BB / 64), 256>>>(states, W2, b2, h1, BB, HID,  SDIM);
    sgemm_bias<true ><<<dim3(HID2 / 64, BB / 64), 256>>>(h1,     W3, b3, h2, BB, HID2, HID);
    sgemm_bias<false><<<dim3(NN   / 64, BB / 64), 256>>>(h2,     W4, b4, logits, BB, NN, HID2);
    softmax_kernel<<<NN, 256>>>(logits, out);
}

// round 3
// speedup vs baseline: 1.1714x; 1.1714x over previous
#include <cuda_runtime.h>

#define BB 2048
#define NN 64
#define EPG 512
#define TOTAL_N (BB*NN)      // 131072
#define TOTAL_E (BB*EPG)     // 1048576
#define DN 16
#define DE 64
#define DU 32
#define DUE 64
#define HID 512
#define HID2 256
#define SDIM (NN*DE + DUE)   // 4160
#define MASK_WORDS (TOTAL_N*DE/32)   // 262144

// ---------------- scratch (no allocs allowed) ----------------
__device__ float g_states[BB*SDIM];   // 34 MB
__device__ float g_h1[BB*HID];
__device__ float g_h2[BB*HID2];
__device__ float g_logits[BB*NN];
__device__ unsigned int g_mask[MASK_WORDS];

// ---------------- threefry2x32 (JAX, key = PRNGKey(42) = {0,42}) ----------------
__device__ __forceinline__ unsigned int rotl32(unsigned int v, int d) {
    return __funnelshift_l(v, v, d);
}

// Full 20-round Threefry-2x32. JAX partitionable 32-bit path returns out0 ^ out1.
__device__ __forceinline__ unsigned int threefry_xor(unsigned int x0, unsigned int x1) {
    const unsigned int K0 = 0u, K1 = 42u;
    const unsigned int K2c = 0x1BD11BDAu ^ K0 ^ K1;
#define TF_ROUND(r) { x0 += x1; x1 = rotl32(x1, r); x1 ^= x0; }
    x0 += K0; x1 += K1;
    TF_ROUND(13) TF_ROUND(15) TF_ROUND(26) TF_ROUND(6)
    x0 += K1;  x1 += K2c + 1u;
    TF_ROUND(17) TF_ROUND(29) TF_ROUND(16) TF_ROUND(24)
    x0 += K2c; x1 += K0 + 2u;
    TF_ROUND(13) TF_ROUND(15) TF_ROUND(26) TF_ROUND(6)
    x0 += K0;  x1 += K1 + 3u;
    TF_ROUND(17) TF_ROUND(29) TF_ROUND(16) TF_ROUND(24)
    x0 += K1;  x1 += K2c + 4u;
    TF_ROUND(13) TF_ROUND(15) TF_ROUND(26) TF_ROUND(6)
    x0 += K2c; x1 += K0 + 5u;
#undef TF_ROUND
    return x0 ^ x1;
}

__global__ void mask_kernel() {
    unsigned int i = blockIdx.x * blockDim.x + threadIdx.x;
    unsigned int bits = threefry_xor(0u, i);
    int keep = (bits >> 31) == 0u;
    unsigned int bal = __ballot_sync(0xffffffffu, keep);
    if ((threadIdx.x & 31) == 0) g_mask[i >> 5] = bal;
}

// ---------------- per-graph GNN kernel ----------------
__global__ __launch_bounds__(256) void graph_kernel(
    const float* __restrict__ x, const float* __restrict__ edge_attr,
    const float* __restrict__ user_s,
    const float* __restrict__ W_msg, const float* __restrict__ b_msg,
    const float* __restrict__ W_edge, const float* __restrict__ b_edge,
    const float* __restrict__ W_self, const float* __restrict__ b_self,
    const float* __restrict__ W1, const float* __restrict__ b1,
    const int* __restrict__ edge_index)
{
    __shared__ float sWm[DN][DE];
    __shared__ float sWs[DN][DE];
    __shared__ float sWe[2][DE];
    __shared__ float sbme[DE];
    __shared__ float sbs[DE];
    __shared__ float sx[NN][DN];
    __shared__ float sxm[NN][DE + 1];
    __shared__ float sA[NN][NN + 1];
    __shared__ float sea[NN][2];

    const int b = blockIdx.x;
    const int t = threadIdx.x;

    for (int i = t; i < DN * DE; i += 256) {
        sWm[i / DE][i % DE] = W_msg[i];
        sWs[i / DE][i % DE] = W_self[i];
    }
    for (int i = t; i < 2 * DE; i += 256) sWe[i / DE][i % DE] = W_edge[i];
    if (t < DE) { sbme[t] = b_msg[t] + b_edge[t]; sbs[t] = b_self[t]; }
    for (int i = t; i < NN * DN; i += 256) sx[i / DN][i % DN] = x[b * NN * DN + i];
    for (int i = t; i < NN * (NN + 1); i += 256) (&sA[0][0])[i] = 0.f;
    if (t < NN) { sea[t][0] = 0.f; sea[t][1] = 0.f; }
    __syncthreads();

    const int n = t >> 2;
    const int d0 = (t & 3) * 16;

    {
        float acc[16];
        #pragma unroll
        for (int j = 0; j < 16; j++) acc[j] = 0.f;
        #pragma unroll
        for (int k = 0; k < DN; k++) {
            float xv = sx[n][k];
            #pragma unroll
            for (int j = 0; j < 16; j++) acc[j] += xv * sWm[k][d0 + j];
        }
        #pragma unroll
        for (int j = 0; j < 16; j++) sxm[n][d0 + j] = acc[j];
    }

    {
        const int ebase = b * EPG;
        for (int e = t; e < EPG; e += 256) {
            int src = edge_index[ebase + e];
            int dst = edge_index[TOTAL_E + ebase + e];
            int sl = src - b * NN;
            int dl = dst - b * NN;
            atomicAdd(&sA[dl][sl], 1.f);
            float ea0 = edge_attr[(ebase + e) * 2];
            float ea1 = edge_attr[(ebase + e) * 2 + 1];
            atomicAdd(&sea[dl][0], ea0);
            atomicAdd(&sea[dl][1], ea1);
        }
    }
    __syncthreads();

    {
        float acc[16];
        #pragma unroll
        for (int j = 0; j < 16; j++) acc[j] = sbs[d0 + j];
        #pragma unroll
        for (int k = 0; k < DN; k++) {
            float xv = sx[n][k];
            #pragma unroll
            for (int j = 0; j < 16; j++) acc[j] += xv * sWs[k][d0 + j];
        }
        float deg = 0.f;
        for (int u = 0; u < NN; u++) {
            float a = sA[n][u];
            deg += a;
            if (a != 0.f) {
                #pragma unroll
                for (int j = 0; j < 16; j++) acc[j] += a * sxm[u][d0 + j];
            }
        }
        float e0 = sea[n][0], e1 = sea[n][1];
        #pragma unroll
        for (int j = 0; j < 16; j++) {
            int d = d0 + j;
            float v = acc[j] + e0 * sWe[0][d] + e1 * sWe[1][d] + deg * sbme[d];
            v = (v > 0.f) ? v * 2.f : 0.f;
            unsigned int idx = (unsigned int)(b * NN + n) * DE + d;
            unsigned int w = g_mask[idx >> 5];
            if (!((w >> (idx & 31)) & 1u)) v = 0.f;
            g_states[b * SDIM + n * DE + d] = v;
        }
    }

    if (t < DUE) {
        float acc = b1[t];
        #pragma unroll
        for (int k = 0; k < DU; k++) acc += user_s[b * DU + k] * W1[k * DUE + t];
        g_states[b * SDIM + NN * DE + t] = fmaxf(acc, 0.f);
    }
}

// ---------------- tf32 tensor-core GEMM ----------------
// C[M,N] = act(A[M,K] @ B[K,N] + bias), row-major. BM=128, BN=64, BK=16, 256 thr.
__device__ __forceinline__ unsigned f2tf(float v) {
    unsigned r; asm("cvt.rna.tf32.f32 %0, %1;" : "=r"(r) : "f"(v)); return r;
}

__device__ __forceinline__ void mma_tf32(float* d, const uint4& a, const uint2& b) {
    asm volatile(
        "mma.sync.aligned.m16n8k8.row.col.f32.tf32.tf32.f32 "
        "{%0,%1,%2,%3}, {%4,%5,%6,%7}, {%8,%9}, {%0,%1,%2,%3};"
        : "+f"(d[0]), "+f"(d[1]), "+f"(d[2]), "+f"(d[3])
        : "r"(a.x), "r"(a.y), "r"(a.z), "r"(a.w), "r"(b.x), "r"(b.y));
}

template <bool RELU>
__global__ __launch_bounds__(256) void tgemm(
    const float* __restrict__ A, const float* __restrict__ Bw,
    const float* __restrict__ bias, float* __restrict__ C,
    int M, int N, int K)
{
    // Fragment-ordered staging: one lds.128 per A frag, lds.64 per B frag.
    __shared__ unsigned sAu[2][16][32][4];   // 16 KB
    __shared__ unsigned sBu[2][16][32][2];   // 8 KB

    const int t = threadIdx.x;
    const int lane = t & 31, wid = t >> 5;
    const int wm = wid >> 2, wn = wid & 3;      // 2 x 4 warp grid
    const int m0 = blockIdx.y * 128, n0 = blockIdx.x * 64;

    // ---- A store mapping (two float4 per thread: rows r0a and r0a+64) ----
    const int r0a = t >> 2, c0a = (t & 3) << 2;        // c0a in {0,4,8,12}
    const int mtA = r0a >> 4, rrA = r0a & 15;
    const int fA  = (mtA << 1) + (c0a >> 3);           // fragment idx for row block mtA
    const int lnA = (rrA & 7) << 2;                    // + jj
    const int rgA = (rrA >> 3) + (((c0a & 7) >> 2) << 1);
    // second row = r0a + 64 -> mtA+4, same rrA bits
    const int fA2 = ((mtA + 4) << 1) + (c0a >> 3);

    // ---- B store mapping (one float4 per thread) ----
    const int krB = t >> 4, c0b = (t & 15) << 2;
    const int fB  = ((c0b >> 3) << 1) + (krB >> 3);
    const int lnB = ((c0b & 7) << 2) + (krB & 3);      // + 4*jj
    const int rgB = (krB >> 2) & 1;

    const float* gA0 = A + (size_t)(m0 + r0a) * K + c0a;
    const float* gA1 = A + (size_t)(m0 + r0a + 64) * K + c0a;
    const float* gB  = Bw + (size_t)krB * N + n0 + c0b;

    float acc[4][2][4];
    #pragma unroll
    for (int i = 0; i < 4; i++)
        #pragma unroll
        for (int j = 0; j < 2; j++)
            #pragma unroll
            for (int k = 0; k < 4; k++) acc[i][j][k] = 0.f;

    const int nIter = K >> 4;

    // prologue: tile 0 -> stage 0
    {
        float4 a0 = *(const float4*)gA0;
        float4 a1 = *(const float4*)gA1;
        float4 bv = *(const float4*)gB;
        gA0 += 16; gA1 += 16; gB += (size_t)16 * N;
        sAu[0][fA ][lnA + 0][rgA] = f2tf(a0.x);
        sAu[0][fA ][lnA + 1][rgA] = f2tf(a0.y);
        sAu[0][fA ][lnA + 2][rgA] = f2tf(a0.z);
        sAu[0][fA ][lnA + 3][rgA] = f2tf(a0.w);
        sAu[0][fA2][lnA + 0][rgA] = f2tf(a1.x);
        sAu[0][fA2][lnA + 1][rgA] = f2tf(a1.y);
        sAu[0][fA2][lnA + 2][rgA] = f2tf(a1.z);
        sAu[0][fA2][lnA + 3][rgA] = f2tf(a1.w);
        sBu[0][fB][lnB +  0][rgB] = f2tf(bv.x);
        sBu[0][fB][lnB +  4][rgB] = f2tf(bv.y);
        sBu[0][fB][lnB +  8][rgB] = f2tf(bv.z);
        sBu[0][fB][lnB + 12][rgB] = f2tf(bv.w);
    }
    __syncthreads();

    for (int it = 0; it < nIter; it++) {
        const int st = it & 1;
        float4 pa0, pa1, pb;
        const bool pre = (it + 1 < nIter);
        if (pre) {
            pa0 = *(const float4*)gA0;
            pa1 = *(const float4*)gA1;
            pb  = *(const float4*)gB;
            gA0 += 16; gA1 += 16; gB += (size_t)16 * N;
        }

        #pragma unroll
        for (int s = 0; s < 2; s++) {
            uint4 af[4];
            uint2 bf[2];
            #pragma unroll
            for (int i = 0; i < 4; i++)
                af[i] = *(const uint4*)&sAu[st][((wm * 4 + i) << 1) + s][lane][0];
            #pragma unroll
            for (int i = 0; i < 2; i++)
                bf[i] = *(const uint2*)&sBu[st][((wn * 2 + i) << 1) + s][lane][0];
            #pragma unroll
            for (int mt = 0; mt < 4; mt++)
                #pragma unroll
                for (int nt = 0; nt < 2; nt++)
                    mma_tf32(acc[mt][nt], af[mt], bf[nt]);
        }

        if (pre) {
            const int ns = st ^ 1;
            sAu[ns][fA ][lnA + 0][rgA] = f2tf(pa0.x);
            sAu[ns][fA ][lnA + 1][rgA] = f2tf(pa0.y);
            sAu[ns][fA ][lnA + 2][rgA] = f2tf(pa0.z);
            sAu[ns][fA ][lnA + 3][rgA] = f2tf(pa0.w);
            sAu[ns][fA2][lnA + 0][rgA] = f2tf(pa1.x);
            sAu[ns][fA2][lnA + 1][rgA] = f2tf(pa1.y);
            sAu[ns][fA2][lnA + 2][rgA] = f2tf(pa1.z);
            sAu[ns][fA2][lnA + 3][rgA] = f2tf(pa1.w);
            sBu[ns][fB][lnB +  0][rgB] = f2tf(pb.x);
            sBu[ns][fB][lnB +  4][rgB] = f2tf(pb.y);
            sBu[ns][fB][lnB +  8][rgB] = f2tf(pb.z);
            sBu[ns][fB][lnB + 12][rgB] = f2tf(pb.w);
        }
        __syncthreads();
    }

    // epilogue
    #pragma unroll
    for (int mt = 0; mt < 4; mt++) {
        int r0 = m0 + wm * 64 + mt * 16 + (lane >> 2);
        #pragma unroll
        for (int nt = 0; nt < 2; nt++) {
            int c = n0 + wn * 16 + nt * 8 + ((lane & 3) << 1);
            float bv0 = bias[c], bv1 = bias[c + 1];
            float v0 = acc[mt][nt][0] + bv0;
            float v1 = acc[mt][nt][1] + bv1;
            float v2 = acc[mt][nt][2] + bv0;
            float v3 = acc[mt][nt][3] + bv1;
            if (RELU) {
                v0 = fmaxf(v0, 0.f); v1 = fmaxf(v1, 0.f);
                v2 = fmaxf(v2, 0.f); v3 = fmaxf(v3, 0.f);
            }
            float2 w0 = {v0, v1}, w1 = {v2, v3};
            *(float2*)&C[(size_t)r0 * N + c] = w0;
            *(float2*)&C[(size_t)(r0 + 8) * N + c] = w1;
        }
    }
}

// ---------------- softmax over the BATCH axis (axis 0 of [B, N]) ----------------
__global__ __launch_bounds__(256) void softmax_kernel(
    const float* __restrict__ logits, float* __restrict__ out)
{
    const int ncol = blockIdx.x;
    const int t = threadIdx.x;
    __shared__ float red[256];

    float mx = -1e30f;
    for (int bi = t; bi < BB; bi += 256) mx = fmaxf(mx, logits[bi * NN + ncol]);
    red[t] = mx; __syncthreads();
    for (int s = 128; s > 0; s >>= 1) { if (t < s) red[t] = fmaxf(red[t], red[t + s]); __syncthreads(); }
    mx = red[0]; __syncthreads();

    float sum = 0.f;
    for (int bi = t; bi < BB; bi += 256) sum += expf(logits[bi * NN + ncol] - mx);
    red[t] = sum; __syncthreads();
    for (int s = 128; s > 0; s >>= 1) { if (t < s) red[t] += red[t + s]; __syncthreads(); }
    float inv = 1.f / red[0];

    for (int bi = t; bi < BB; bi += 256)
        out[bi * NN + ncol] = expf(logits[bi * NN + ncol] - mx) * inv;
}

// ---------------- launch ----------------
extern "C" void kernel_launch(void* const* d_in, const int* in_sizes, int n_in,
                              void* d_out, int out_size)
{
    const float* x         = (const float*)d_in[0];
    const float* edge_attr = (const float*)d_in[1];
    const float* user_s    = (const float*)d_in[2];
    const float* W_msg     = (const float*)d_in[3];
    const float* b_msg     = (const float*)d_in[4];
    const float* W_edge    = (const float*)d_in[5];
    const float* b_edge    = (const float*)d_in[6];
    const float* W_self    = (const float*)d_in[7];
    const float* b_self    = (const float*)d_in[8];
    const float* W1        = (const float*)d_in[9];
    const float* b1        = (const float*)d_in[10];
    const float* W2        = (const float*)d_in[11];
    const float* b2        = (const float*)d_in[12];
    const float* W3        = (const float*)d_in[13];
    const float* b3        = (const float*)d_in[14];
    const float* W4        = (const float*)d_in[15];
    const float* b4        = (const float*)d_in[16];
    const int*   edge_index = (const int*)d_in[17];
    float* out = (float*)d_out;

    float *states, *h1, *h2, *logits;
    cudaGetSymbolAddress((void**)&states, g_states);
    cudaGetSymbolAddress((void**)&h1, g_h1);
    cudaGetSymbolAddress((void**)&h2, g_h2);
    cudaGetSymbolAddress((void**)&logits, g_logits);

    mask_kernel<<<TOTAL_N * DE / 256, 256>>>();
    graph_kernel<<<BB, 256>>>(x, edge_attr, user_s, W_msg, b_msg, W_edge, b_edge,
                              W_self, b_self, W1, b1, edge_index);
    tgemm<true ><<<dim3(HID  / 64, BB / 128), 256>>>(states, W2, b2, h1, BB, HID,  SDIM);
    tgemm<true ><<<dim3(HID2 / 64, BB / 128), 256>>>(h1,     W3, b3, h2, BB, HID2, HID);
    tgemm<false><<<dim3(NN   / 64, BB / 128), 256>>>(h2,     W4, b4, logits, BB, NN, HID2);
    softmax_kernel<<<NN, 256>>>(logits, out);
}

// round 4
// speedup vs baseline: 1.7429x; 1.4879x over previous
#include <cuda_runtime.h>

#define BB 2048
#define NN 64
#define EPG 512
#define TOTAL_N (BB*NN)      // 131072
#define TOTAL_E (BB*EPG)     // 1048576
#define DN 16
#define DE 64
#define DU 32
#define DUE 64
#define HID 512
#define HID2 256
#define SDIM (NN*DE + DUE)   // 4160
#define MASK_WORDS (TOTAL_N*DE/32)   // 262144

// ---------------- scratch (no allocs allowed) ----------------
__device__ float g_states[BB*SDIM];   // 34 MB
__device__ float g_h1[BB*HID];
__device__ float g_h2[BB*HID2];
__device__ float g_logits[BB*NN];
__device__ unsigned int g_mask[MASK_WORDS];
__device__ float g_w2[SDIM*HID];      // tf32-rounded weights
__device__ float g_w3[HID*HID2];
__device__ float g_w4[HID2*NN];

// ---------------- helpers ----------------
__device__ __forceinline__ unsigned f2tf(float v) {
    unsigned r; asm("cvt.rna.tf32.f32 %0, %1;" : "=r"(r) : "f"(v)); return r;
}
__device__ __forceinline__ float f2tff(float v) { return __uint_as_float(f2tf(v)); }
__device__ __forceinline__ unsigned s2u(const void* p) {
    return (unsigned)__cvta_generic_to_shared(p);
}

__global__ void cvt_kernel(const float* __restrict__ src, float* __restrict__ dst, int n) {
    int i = blockIdx.x * blockDim.x + threadIdx.x;
    if (i < n) dst[i] = f2tff(src[i]);
}

// ---------------- threefry2x32 (JAX, key = PRNGKey(42) = {0,42}) ----------------
__device__ __forceinline__ unsigned int rotl32(unsigned int v, int d) {
    return __funnelshift_l(v, v, d);
}

__device__ __forceinline__ unsigned int threefry_xor(unsigned int x0, unsigned int x1) {
    const unsigned int K0 = 0u, K1 = 42u;
    const unsigned int K2c = 0x1BD11BDAu ^ K0 ^ K1;
#define TF_ROUND(r) { x0 += x1; x1 = rotl32(x1, r); x1 ^= x0; }
    x0 += K0; x1 += K1;
    TF_ROUND(13) TF_ROUND(15) TF_ROUND(26) TF_ROUND(6)
    x0 += K1;  x1 += K2c + 1u;
    TF_ROUND(17) TF_ROUND(29) TF_ROUND(16) TF_ROUND(24)
    x0 += K2c; x1 += K0 + 2u;
    TF_ROUND(13) TF_ROUND(15) TF_ROUND(26) TF_ROUND(6)
    x0 += K0;  x1 += K1 + 3u;
    TF_ROUND(17) TF_ROUND(29) TF_ROUND(16) TF_ROUND(24)
    x0 += K1;  x1 += K2c + 4u;
    TF_ROUND(13) TF_ROUND(15) TF_ROUND(26) TF_ROUND(6)
    x0 += K2c; x1 += K0 + 5u;
#undef TF_ROUND
    return x0 ^ x1;
}

__global__ void mask_kernel() {
    unsigned int i = blockIdx.x * blockDim.x + threadIdx.x;
    unsigned int bits = threefry_xor(0u, i);
    int keep = (bits >> 31) == 0u;
    unsigned int bal = __ballot_sync(0xffffffffu, keep);
    if ((threadIdx.x & 31) == 0) g_mask[i >> 5] = bal;
}

// ---------------- per-graph GNN kernel ----------------
__global__ __launch_bounds__(256) void graph_kernel(
    const float* __restrict__ x, const float* __restrict__ edge_attr,
    const float* __restrict__ user_s,
    const float* __restrict__ W_msg, const float* __restrict__ b_msg,
    const float* __restrict__ W_edge, const float* __restrict__ b_edge,
    const float* __restrict__ W_self, const float* __restrict__ b_self,
    const float* __restrict__ W1, const float* __restrict__ b1,
    const int* __restrict__ edge_index)
{
    __shared__ float sWm[DN][DE];
    __shared__ float sWs[DN][DE];
    __shared__ float sWe[2][DE];
    __shared__ float sbme[DE];
    __shared__ float sbs[DE];
    __shared__ float sx[NN][DN];
    __shared__ float sxm[NN][DE + 1];
    __shared__ float sA[NN][NN + 1];
    __shared__ float sea[NN][2];

    const int b = blockIdx.x;
    const int t = threadIdx.x;

    for (int i = t; i < DN * DE; i += 256) {
        sWm[i / DE][i % DE] = W_msg[i];
        sWs[i / DE][i % DE] = W_self[i];
    }
    for (int i = t; i < 2 * DE; i += 256) sWe[i / DE][i % DE] = W_edge[i];
    if (t < DE) { sbme[t] = b_msg[t] + b_edge[t]; sbs[t] = b_self[t]; }
    for (int i = t; i < NN * DN; i += 256) sx[i / DN][i % DN] = x[b * NN * DN + i];
    for (int i = t; i < NN * (NN + 1); i += 256) (&sA[0][0])[i] = 0.f;
    if (t < NN) { sea[t][0] = 0.f; sea[t][1] = 0.f; }
    __syncthreads();

    const int n = t >> 2;
    const int d0 = (t & 3) * 16;

    {
        float acc[16];
        #pragma unroll
        for (int j = 0; j < 16; j++) acc[j] = 0.f;
        #pragma unroll
        for (int k = 0; k < DN; k++) {
            float xv = sx[n][k];
            #pragma unroll
            for (int j = 0; j < 16; j++) acc[j] += xv * sWm[k][d0 + j];
        }
        #pragma unroll
        for (int j = 0; j < 16; j++) sxm[n][d0 + j] = acc[j];
    }

    {
        const int ebase = b * EPG;
        for (int e = t; e < EPG; e += 256) {
            int src = edge_index[ebase + e];
            int dst = edge_index[TOTAL_E + ebase + e];
            int sl = src - b * NN;
            int dl = dst - b * NN;
            atomicAdd(&sA[dl][sl], 1.f);
            float ea0 = edge_attr[(ebase + e) * 2];
            float ea1 = edge_attr[(ebase + e) * 2 + 1];
            atomicAdd(&sea[dl][0], ea0);
            atomicAdd(&sea[dl][1], ea1);
        }
    }
    __syncthreads();

    {
        float acc[16];
        #pragma unroll
        for (int j = 0; j < 16; j++) acc[j] = sbs[d0 + j];
        #pragma unroll
        for (int k = 0; k < DN; k++) {
            float xv = sx[n][k];
            #pragma unroll
            for (int j = 0; j < 16; j++) acc[j] += xv * sWs[k][d0 + j];
        }
        float deg = 0.f;
        for (int u = 0; u < NN; u++) {
            float a = sA[n][u];
            deg += a;
            if (a != 0.f) {
                #pragma unroll
                for (int j = 0; j < 16; j++) acc[j] += a * sxm[u][d0 + j];
            }
        }
        float e0 = sea[n][0], e1 = sea[n][1];
        #pragma unroll
        for (int j = 0; j < 16; j++) {
            int d = d0 + j;
            float v = acc[j] + e0 * sWe[0][d] + e1 * sWe[1][d] + deg * sbme[d];
            v = (v > 0.f) ? v * 2.f : 0.f;
            unsigned int idx = (unsigned int)(b * NN + n) * DE + d;
            unsigned int w = g_mask[idx >> 5];
            if (!((w >> (idx & 31)) & 1u)) v = 0.f;
            g_states[b * SDIM + n * DE + d] = f2tff(v);   // tf32-round for GEMM1
        }
    }

    if (t < DUE) {
        float acc = b1[t];
        #pragma unroll
        for (int k = 0; k < DU; k++) acc += user_s[b * DU + k] * W1[k * DUE + t];
        g_states[b * SDIM + NN * DE + t] = f2tff(fmaxf(acc, 0.f));
    }
}

// ---------------- tf32 tensor-core GEMM, cp.async 3-stage pipeline ----------------
// C[M,N] = act(A[M,K] @ B[K,N] + bias). BM=128, BN=64, BK=32, 256 thr (4m x 2n warps).
__device__ __forceinline__ void mma_tf32(float* d, const uint4& a, unsigned b0, unsigned b1) {
    asm volatile(
        "mma.sync.aligned.m16n8k8.row.col.f32.tf32.tf32.f32 "
        "{%0,%1,%2,%3}, {%4,%5,%6,%7}, {%8,%9}, {%0,%1,%2,%3};"
        : "+f"(d[0]), "+f"(d[1]), "+f"(d[2]), "+f"(d[3])
        : "r"(a.x), "r"(a.y), "r"(a.z), "r"(a.w), "r"(b0), "r"(b1));
}
__device__ __forceinline__ void ldsm4(uint4& r, unsigned addr) {
    asm volatile("ldmatrix.sync.aligned.m8n8.x4.shared.b16 {%0,%1,%2,%3}, [%4];"
                 : "=r"(r.x), "=r"(r.y), "=r"(r.z), "=r"(r.w) : "r"(addr));
}
#define CPA16(dst, src) asm volatile("cp.async.cg.shared.global [%0], [%1], 16;" :: "r"(dst), "l"(src))
#define CPA_COMMIT()    asm volatile("cp.async.commit_group;" ::: "memory")
#define CPA_WAIT1()     asm volatile("cp.async.wait_group 1;" ::: "memory")

#define TG_STG_A 16384            // bytes per A stage (128 rows x 128B, swizzled)
#define TG_STG_BF 2304            // floats per B stage (32 rows x 72)
#define TG_SMEM (3*TG_STG_A + 3*TG_STG_BF*4)   // 76800 B

template <bool RELU, bool CVT_OUT>
__global__ __launch_bounds__(256) void tgemm(
    const float* __restrict__ A, const float* __restrict__ Bw,
    const float* __restrict__ bias, float* __restrict__ C,
    int M, int N, int K)
{
    extern __shared__ char smem[];
    float* sB = (float*)(smem + 3 * TG_STG_A);
    const unsigned sAu = s2u(smem);
    const unsigned sBu = s2u(sB);

    const int t = threadIdx.x, lane = t & 31, wid = t >> 5;
    const int wm = wid >> 1, wn = wid & 1;            // 4m x 2n
    const int m0 = blockIdx.y * 128, n0 = blockIdx.x * 64;

    // cp.async source pointers (per-thread fixed row/granule)
    const int arow[4] = { (t+  0)>>3, (t+256)>>3, (t+512)>>3, (t+768)>>3 };
    const int agr [4] = { t&7, t&7, t&7, t&7 };       // (t+256j)&7 == t&7
    const int brow[2] = { t>>4, (t+256)>>4 };
    const int bgr = t & 15;

    // A frag ldmatrix rows (fixed per mt): lanes 0-7,8-15 -> rows +0..15 ; 16-31 repeat
    int rA[2], rbA[2], swA[2];
    #pragma unroll
    for (int mt = 0; mt < 2; mt++) {
        rA[mt]  = wm * 32 + mt * 16 + (lane & 7) + (((lane >> 3) & 1) << 3);
        rbA[mt] = rA[mt] << 7;                        // row * 128 bytes
        swA[mt] = rA[mt] & 7;
    }
    const int csel = lane >> 4;                       // 0: cols k..k+3, 1: k+4..k+7
    const int bkr  = lane & 3;                        // B frag k row within 8
    const int bnc  = wn * 32 + (lane >> 2);           // B frag n col base

    float acc[2][4][4];
    #pragma unroll
    for (int i = 0; i < 2; i++)
        #pragma unroll
        for (int j = 0; j < 4; j++)
            #pragma unroll
            for (int k = 0; k < 4; k++) acc[i][j][k] = 0.f;

    const int nIter = K >> 5;

    // ---- stage issue ----
    #define ISSUE(st, k0)                                                          \
    {                                                                              \
        _Pragma("unroll")                                                          \
        for (int j = 0; j < 4; j++) {                                              \
            unsigned d = sAu + (st) * TG_STG_A + (arow[j] << 7)                    \
                       + (((agr[j] ^ (arow[j] & 7))) << 4);                        \
            CPA16(d, A + (size_t)(m0 + arow[j]) * K + (k0) + (agr[j] << 2));       \
        }                                                                          \
        _Pragma("unroll")                                                          \
        for (int j = 0; j < 2; j++) {                                              \
            unsigned d = sBu + (st) * (TG_STG_BF * 4) + brow[j] * 288 + (bgr << 4);\
            CPA16(d, Bw + (size_t)((k0) + brow[j]) * N + n0 + (bgr << 2));         \
        }                                                                          \
    }

    ISSUE(0, 0); CPA_COMMIT();
    ISSUE(1, 32); CPA_COMMIT();

    for (int it = 0; it < nIter; it++) {
        const int st = it % 3;
        CPA_WAIT1();
        __syncthreads();

        const unsigned aBase = sAu + st * TG_STG_A;
        const float* bBase = sB + st * TG_STG_BF;

        #pragma unroll
        for (int s = 0; s < 4; s++) {
            uint4 af[2];
            #pragma unroll
            for (int mt = 0; mt < 2; mt++) {
                unsigned ad = aBase + rbA[mt] + ((((s << 1) + csel) ^ swA[mt]) << 4);
                ldsm4(af[mt], ad);
            }
            const int kr = (s << 3) + bkr;
            unsigned b0[4], b1[4];
            #pragma unroll
            for (int nt = 0; nt < 4; nt++) {
                b0[nt] = __float_as_uint(bBase[kr * 72 + bnc + nt * 8]);
                b1[nt] = __float_as_uint(bBase[(kr + 4) * 72 + bnc + nt * 8]);
            }
            #pragma unroll
            for (int mt = 0; mt < 2; mt++)
                #pragma unroll
                for (int nt = 0; nt < 4; nt++)
                    mma_tf32(acc[mt][nt], af[mt], b0[nt], b1[nt]);
        }

        if (it + 2 < nIter) { const int ns = (it + 2) % 3; ISSUE(ns, (it + 2) << 5); }
        CPA_COMMIT();
    }
    #undef ISSUE

    // epilogue
    #pragma unroll
    for (int mt = 0; mt < 2; mt++) {
        int r0 = m0 + wm * 32 + mt * 16 + (lane >> 2);
        #pragma unroll
        for (int nt = 0; nt < 4; nt++) {
            int c = n0 + wn * 32 + nt * 8 + ((lane & 3) << 1);
            float bv0 = bias[c], bv1 = bias[c + 1];
            float v0 = acc[mt][nt][0] + bv0;
            float v1 = acc[mt][nt][1] + bv1;
            float v2 = acc[mt][nt][2] + bv0;
            float v3 = acc[mt][nt][3] + bv1;
            if (RELU) {
                v0 = fmaxf(v0, 0.f); v1 = fmaxf(v1, 0.f);
                v2 = fmaxf(v2, 0.f); v3 = fmaxf(v3, 0.f);
            }
            if (CVT_OUT) {
                v0 = f2tff(v0); v1 = f2tff(v1); v2 = f2tff(v2); v3 = f2tff(v3);
            }
            float2 w0 = {v0, v1}, w1 = {v2, v3};
            *(float2*)&C[(size_t)r0 * N + c] = w0;
            *(float2*)&C[(size_t)(r0 + 8) * N + c] = w1;
        }
    }
}

// ---------------- softmax over the BATCH axis (axis 0 of [B, N]) ----------------
__global__ __launch_bounds__(256) void softmax_kernel(
    const float* __restrict__ logits, float* __restrict__ out)
{
    const int ncol = blockIdx.x;
    const int t = threadIdx.x;
    __shared__ float red[256];

    float mx = -1e30f;
    for (int bi = t; bi < BB; bi += 256) mx = fmaxf(mx, logits[bi * NN + ncol]);
    red[t] = mx; __syncthreads();
    for (int s = 128; s > 0; s >>= 1) { if (t < s) red[t] = fmaxf(red[t], red[t + s]); __syncthreads(); }
    mx = red[0]; __syncthreads();

    float sum = 0.f;
    for (int bi = t; bi < BB; bi += 256) sum += expf(logits[bi * NN + ncol] - mx);
    red[t] = sum; __syncthreads();
    for (int s = 128; s > 0; s >>= 1) { if (t < s) red[t] += red[t + s]; __syncthreads(); }
    float inv = 1.f / red[0];

    for (int bi = t; bi < BB; bi += 256)
        out[bi * NN + ncol] = expf(logits[bi * NN + ncol] - mx) * inv;
}

// ---------------- launch ----------------
extern "C" void kernel_launch(void* const* d_in, const int* in_sizes, int n_in,
                              void* d_out, int out_size)
{
    const float* x         = (const float*)d_in[0];
    const float* edge_attr = (const float*)d_in[1];
    const float* user_s    = (const float*)d_in[2];
    const float* W_msg     = (const float*)d_in[3];
    const float* b_msg     = (const float*)d_in[4];
    const float* W_edge    = (const float*)d_in[5];
    const float* b_edge    = (const float*)d_in[6];
    const float* W_self    = (const float*)d_in[7];
    const float* b_self    = (const float*)d_in[8];
    const float* W1        = (const float*)d_in[9];
    const float* b1        = (const float*)d_in[10];
    const float* W2        = (const float*)d_in[11];
    const float* b2        = (const float*)d_in[12];
    const float* W3        = (const float*)d_in[13];
    const float* b3        = (const float*)d_in[14];
    const float* W4        = (const float*)d_in[15];
    const float* b4        = (const float*)d_in[16];
    const int*   edge_index = (const int*)d_in[17];
    float* out = (float*)d_out;

    float *states, *h1, *h2, *logits, *w2c, *w3c, *w4c;
    cudaGetSymbolAddress((void**)&states, g_states);
    cudaGetSymbolAddress((void**)&h1, g_h1);
    cudaGetSymbolAddress((void**)&h2, g_h2);
    cudaGetSymbolAddress((void**)&logits, g_logits);
    cudaGetSymbolAddress((void**)&w2c, g_w2);
    cudaGetSymbolAddress((void**)&w3c, g_w3);
    cudaGetSymbolAddress((void**)&w4c, g_w4);

    cudaFuncSetAttribute(tgemm<true, true>,
                         cudaFuncAttributeMaxDynamicSharedMemorySize, TG_SMEM);
    cudaFuncSetAttribute(tgemm<false, false>,
                         cudaFuncAttributeMaxDynamicSharedMemorySize, TG_SMEM);

    cvt_kernel<<<(SDIM*HID + 255) / 256, 256>>>(W2, w2c, SDIM*HID);
    cvt_kernel<<<(HID*HID2 + 255) / 256, 256>>>(W3, w3c, HID*HID2);
    cvt_kernel<<<(HID2*NN + 255) / 256, 256>>>(W4, w4c, HID2*NN);

    mask_kernel<<<TOTAL_N * DE / 256, 256>>>();
    graph_kernel<<<BB, 256>>>(x, edge_attr, user_s, W_msg, b_msg, W_edge, b_edge,
                              W_self, b_self, W1, b1, edge_index);

    tgemm<true , true ><<<dim3(HID  / 64, BB / 128), 256, TG_SMEM>>>(states, w2c, b2, h1, BB, HID,  SDIM);
    tgemm<true , true ><<<dim3(HID2 / 64, BB / 128), 256, TG_SMEM>>>(h1,     w3c, b3, h2, BB, HID2, HID);
    tgemm<false, false><<<dim3(NN   / 64, BB / 128), 256, TG_SMEM>>>(h2,     w4c, b4, logits, BB, NN, HID2);
    softmax_kernel<<<NN, 256>>>(logits, out);
}

// round 8
// speedup vs baseline: 2.4831x; 1.4247x over previous
#include <cuda_runtime.h>

#define BB 2048
#define NN 64
#define EPG 512
#define TOTAL_N (BB*NN)      // 131072
#define TOTAL_E (BB*EPG)     // 1048576
#define DN 16
#define DE 64
#define DU 32
#define DUE 64
#define HID 512
#define HID2 256
#define SDIM (NN*DE + DUE)   // 4160

// ---------------- scratch (no allocs allowed) ----------------
__device__ float g_states[BB*SDIM];   // 34 MB
__device__ float g_h1[BB*HID];
__device__ float g_h2[BB*HID2];
__device__ float g_logits[BB*NN];

// ---------------- helpers ----------------
__device__ __forceinline__ unsigned s2u(const void* p) {
    return (unsigned)__cvta_generic_to_shared(p);
}

// ---------------- threefry2x32 (JAX, key = PRNGKey(42) = {0,42}) ----------------
__device__ __forceinline__ unsigned int rotl32(unsigned int v, int d) {
    return __funnelshift_l(v, v, d);
}

__device__ __forceinline__ unsigned int threefry_xor(unsigned int x0, unsigned int x1) {
    const unsigned int K0 = 0u, K1 = 42u;
    const unsigned int K2c = 0x1BD11BDAu ^ K0 ^ K1;
#define TF_ROUND(r) { x0 += x1; x1 = rotl32(x1, r); x1 ^= x0; }
    x0 += K0; x1 += K1;
    TF_ROUND(13) TF_ROUND(15) TF_ROUND(26) TF_ROUND(6)
    x0 += K1;  x1 += K2c + 1u;
    TF_ROUND(17) TF_ROUND(29) TF_ROUND(16) TF_ROUND(24)
    x0 += K2c; x1 += K0 + 2u;
    TF_ROUND(13) TF_ROUND(15) TF_ROUND(26) TF_ROUND(6)
    x0 += K0;  x1 += K1 + 3u;
    TF_ROUND(17) TF_ROUND(29) TF_ROUND(16) TF_ROUND(24)
    x0 += K1;  x1 += K2c + 4u;
    TF_ROUND(13) TF_ROUND(15) TF_ROUND(26) TF_ROUND(6)
    x0 += K2c; x1 += K0 + 5u;
#undef TF_ROUND
    return x0 ^ x1;
}

// ---------------- per-graph GNN kernel (CSR aggregation + fused dropout mask) ----
__global__ __launch_bounds__(256) void graph_kernel(
    const float* __restrict__ x, const float* __restrict__ edge_attr,
    const float* __restrict__ user_s,
    const float* __restrict__ W_msg, const float* __restrict__ b_msg,
    const float* __restrict__ W_edge, const float* __restrict__ b_edge,
    const float* __restrict__ W_self, const float* __restrict__ b_self,
    const float* __restrict__ W1, const float* __restrict__ b1,
    const int* __restrict__ edge_index)
{
    __shared__ float sWm[DN][DE];
    __shared__ float sWs[DN][DE];
    __shared__ float sWe[2][DE];
    __shared__ float sbme[DE];
    __shared__ float sbs[DE];
    __shared__ float sx[NN][DN];
    __shared__ __align__(16) float sxm[NN][68];   // x@W_msg, stride 68 (16B-aligned rows)
    __shared__ float sea[NN][2];
    __shared__ int   sedge[EPG];
    __shared__ short slist[EPG];
    __shared__ int   sdeg[NN];
    __shared__ int   soff[NN];
    __shared__ int   sfill[NN];

    const int b = blockIdx.x;
    const int t = threadIdx.x;

    for (int i = t; i < DN * DE; i += 256) {
        sWm[i / DE][i % DE] = W_msg[i];
        sWs[i / DE][i % DE] = W_self[i];
    }
    for (int i = t; i < 2 * DE; i += 256) sWe[i / DE][i % DE] = W_edge[i];
    if (t < DE) { sbme[t] = b_msg[t] + b_edge[t]; sbs[t] = b_self[t]; }
    for (int i = t; i < NN * DN; i += 256) sx[i / DN][i % DN] = x[b * NN * DN + i];
    if (t < NN) { sdeg[t] = 0; sfill[t] = 0; sea[t][0] = 0.f; sea[t][1] = 0.f; }
    __syncthreads();

    const int n = t >> 2;
    const int d0 = (t & 3) * 16;

    // xm = x @ W_msg  -> sxm
    {
        float acc[16];
        #pragma unroll
        for (int j = 0; j < 16; j++) acc[j] = 0.f;
        #pragma unroll
        for (int k = 0; k < DN; k++) {
            float xv = sx[n][k];
            #pragma unroll
            for (int j = 0; j < 16; j++) acc[j] += xv * sWm[k][d0 + j];
        }
        #pragma unroll
        for (int j = 0; j < 16; j++) sxm[n][d0 + j] = acc[j];
    }

    // pass 1: stash edges, count degrees, aggregate edge attrs at dst
    {
        const int ebase = b * EPG;
        for (int e = t; e < EPG; e += 256) {
            int src = edge_index[ebase + e] - b * NN;
            int dst = edge_index[TOTAL_E + ebase + e] - b * NN;
            sedge[e] = (src << 8) | dst;
            atomicAdd(&sdeg[dst], 1);
            float2 ea = ((const float2*)edge_attr)[ebase + e];
            atomicAdd(&sea[dst][0], ea.x);
            atomicAdd(&sea[dst][1], ea.y);
        }
    }
    __syncthreads();

    // exclusive scan of degrees (warp 0, 2 values/lane)
    if (t < 32) {
        int a = sdeg[2 * t], bv = sdeg[2 * t + 1];
        int s = a + bv;
        int xsc = s;
        #pragma unroll
        for (int d = 1; d < 32; d <<= 1) {
            int y = __shfl_up_sync(0xffffffffu, xsc, d);
            if (t >= d) xsc += y;
        }
        int excl = xsc - s;
        soff[2 * t] = excl;
        soff[2 * t + 1] = excl + a;
    }
    __syncthreads();

    // pass 2: fill CSR lists
    for (int e = t; e < EPG; e += 256) {
        int pk = sedge[e];
        int dst = pk & 0xff;
        int pos = atomicAdd(&sfill[dst], 1);
        slist[soff[dst] + pos] = (short)(pk >> 8);
    }
    __syncthreads();

    // dropout mask bits for this thread's 16 elements (kept out of unrolled code)
    unsigned mbits = 0;
    {
        unsigned base_idx = ((unsigned)(b * NN + n) << 6) + d0;
        #pragma unroll 1
        for (int j = 0; j < 16; j++)
            mbits |= (((~threefry_xor(0u, base_idx + j)) >> 31) & 1u) << j;
    }

    // aggregate: acc = b_self + x@W_self + sum_{neighbors} xm[src]
    {
        float acc[16];
        #pragma unroll
        for (int j = 0; j < 16; j++) acc[j] = sbs[d0 + j];
        #pragma unroll
        for (int k = 0; k < DN; k++) {
            float xv = sx[n][k];
            #pragma unroll
            for (int j = 0; j < 16; j++) acc[j] += xv * sWs[k][d0 + j];
        }
        const int cnt = sdeg[n], base = soff[n];
        for (int i = 0; i < cnt; i++) {
            int s = slist[base + i];
            const float4* r = (const float4*)&sxm[s][d0];
            float4 r0 = r[0], r1 = r[1], r2 = r[2], r3 = r[3];
            acc[0]  += r0.x; acc[1]  += r0.y; acc[2]  += r0.z; acc[3]  += r0.w;
            acc[4]  += r1.x; acc[5]  += r1.y; acc[6]  += r1.z; acc[7]  += r1.w;
            acc[8]  += r2.x; acc[9]  += r2.y; acc[10] += r2.z; acc[11] += r2.w;
            acc[12] += r3.x; acc[13] += r3.y; acc[14] += r3.z; acc[15] += r3.w;
        }
        const float deg = (float)cnt;
        const float e0 = sea[n][0], e1 = sea[n][1];
        #pragma unroll
        for (int j = 0; j < 16; j++) {
            int d = d0 + j;
            float v = acc[j] + e0 * sWe[0][d] + e1 * sWe[1][d] + deg * sbme[d];
            v = (v > 0.f) ? v * 2.f : 0.f;
            if (!((mbits >> j) & 1u)) v = 0.f;
            g_states[b * SDIM + n * DE + d] = v;
        }
    }

    // user embedding: relu(user_s @ W1 + b1) -> states[b][4096:4160]
    if (t < DUE) {
        float acc = b1[t];
        #pragma unroll
        for (int k = 0; k < DU; k++) acc += user_s[b * DU + k] * W1[k * DUE + t];
        g_states[b * SDIM + NN * DE + t] = fmaxf(acc, 0.f);
    }
}

// ---------------- tf32 tensor-core GEMM, cp.async 3-stage pipeline ----------------
// C[M,N] = act(A[M,K] @ B[K,N] + bias). BM=64, BN=64, BK=32, 256 thr (2m x 4n warps).
__device__ __forceinline__ void mma_tf32(float* d, const uint4& a, unsigned b0, unsigned b1) {
    asm volatile(
        "mma.sync.aligned.m16n8k8.row.col.f32.tf32.tf32.f32 "
        "{%0,%1,%2,%3}, {%4,%5,%6,%7}, {%8,%9}, {%0,%1,%2,%3};"
        : "+f"(d[0]), "+f"(d[1]), "+f"(d[2]), "+f"(d[3])
        : "r"(a.x), "r"(a.y), "r"(a.z), "r"(a.w), "r"(b0), "r"(b1));
}
__device__ __forceinline__ void ldsm4(uint4& r, unsigned addr) {
    asm volatile("ldmatrix.sync.aligned.m8n8.x4.shared.b16 {%0,%1,%2,%3}, [%4];"
                 : "=r"(r.x), "=r"(r.y), "=r"(r.z), "=r"(r.w) : "r"(addr));
}
#define CPA16(dst, src) asm volatile("cp.async.cg.shared.global [%0], [%1], 16;" :: "r"(dst), "l"(src))
#define CPA_COMMIT()    asm volatile("cp.async.commit_group;" ::: "memory")
#define CPA_WAIT1()     asm volatile("cp.async.wait_group 1;" ::: "memory")

#define TG_STG_A 8192             // bytes per A stage (64 rows x 128B, swizzled)
#define TG_STG_BF 2304            // floats per B stage (32 rows x 72)
#define TG_SMEM (3*TG_STG_A + 3*TG_STG_BF*4)   // 52224 B

template <bool RELU>
__global__ __launch_bounds__(256) void tgemm(
    const float* __restrict__ A, const float* __restrict__ Bw,
    const float* __restrict__ bias, float* __restrict__ C,
    int M, int N, int K)
{
    extern __shared__ char smem[];
    float* sB = (float*)(smem + 3 * TG_STG_A);
    const unsigned sAu = s2u(smem);
    const unsigned sBu = s2u(sB);

    const int t = threadIdx.x, lane = t & 31, wid = t >> 5;
    const int wm = wid >> 2, wn = wid & 3;            // 2m x 4n
    const int m0 = blockIdx.y * 64, n0 = blockIdx.x * 64;

    // cp.async per-thread fixed coords: A 64x8 granules (2/thr), B 32x16 granules (2/thr)
    const int ar0 = t >> 3, ag = t & 7;               // rows ar0, ar0+32
    const int br0 = t >> 4, bg = t & 15;              // rows br0, br0+16

    // ldmatrix A rows per m-tile
    int rbA[2], swA[2];
    #pragma unroll
    for (int mt = 0; mt < 2; mt++) {
        int rA = wm * 32 + mt * 16 + (lane & 7) + (((lane >> 3) & 1) << 3);
        rbA[mt] = rA << 7;
        swA[mt] = rA & 7;
    }
    const int csel = lane >> 4;
    const int bkr  = lane & 3;
    const int bnc  = wn * 16 + (lane >> 2);

    float acc[2][2][4];
    #pragma unroll
    for (int i = 0; i < 2; i++)
        #pragma unroll
        for (int j = 0; j < 2; j++)
            #pragma unroll
            for (int k = 0; k < 4; k++) acc[i][j][k] = 0.f;

    const int nIter = K >> 5;

    #define ISSUE(st, k0)                                                          \
    {                                                                              \
        _Pragma("unroll")                                                          \
        for (int j = 0; j < 2; j++) {                                              \
            int r = ar0 + j * 32;                                                  \
            unsigned d = sAu + (st) * TG_STG_A + (r << 7) + ((ag ^ (r & 7)) << 4); \
            CPA16(d, A + (size_t)(m0 + r) * K + (k0) + (ag << 2));                 \
        }                                                                          \
        _Pragma("unroll")                                                          \
        for (int j = 0; j < 2; j++) {                                              \
            int r = br0 + j * 16;                                                  \
            unsigned d = sBu + (st) * (TG_STG_BF * 4) + r * 288 + (bg << 4);       \
            CPA16(d, Bw + (size_t)((k0) + r) * N + n0 + (bg << 2));                \
        }                                                                          \
    }

    ISSUE(0, 0); CPA_COMMIT();
    ISSUE(1, 32); CPA_COMMIT();

    for (int it = 0; it < nIter; it++) {
        const int st = it % 3;
        CPA_WAIT1();
        __syncthreads();

        const unsigned aBase = sAu + st * TG_STG_A;
        const float* bBase = sB + st * TG_STG_BF;

        #pragma unroll
        for (int s = 0; s < 4; s++) {
            uint4 af[2];
            #pragma unroll
            for (int mt = 0; mt < 2; mt++) {
                unsigned ad = aBase + rbA[mt] + ((((s << 1) + csel) ^ swA[mt]) << 4);
                ldsm4(af[mt], ad);
            }
            const int kr = (s << 3) + bkr;
            unsigned b0[2], b1[2];
            #pragma unroll
            for (int nt = 0; nt < 2; nt++) {
                b0[nt] = __float_as_uint(bBase[kr * 72 + bnc + nt * 8]);
                b1[nt] = __float_as_uint(bBase[(kr + 4) * 72 + bnc + nt * 8]);
            }
            #pragma unroll
            for (int mt = 0; mt < 2; mt++)
                #pragma unroll
                for (int nt = 0; nt < 2; nt++)
                    mma_tf32(acc[mt][nt], af[mt], b0[nt], b1[nt]);
        }

        if (it + 2 < nIter) { const int ns = (it + 2) % 3; ISSUE(ns, (it + 2) << 5); }
        CPA_COMMIT();
    }
    #undef ISSUE

    // epilogue
    #pragma unroll
    for (int mt = 0; mt < 2; mt++) {
        int r0 = m0 + wm * 32 + mt * 16 + (lane >> 2);
        #pragma unroll
        for (int nt = 0; nt < 2; nt++) {
            int c = n0 + wn * 16 + nt * 8 + ((lane & 3) << 1);
            float bv0 = bias[c], bv1 = bias[c + 1];
            float v0 = acc[mt][nt][0] + bv0;
            float v1 = acc[mt][nt][1] + bv1;
            float v2 = acc[mt][nt][2] + bv0;
            float v3 = acc[mt][nt][3] + bv1;
            if (RELU) {
                v0 = fmaxf(v0, 0.f); v1 = fmaxf(v1, 0.f);
                v2 = fmaxf(v2, 0.f); v3 = fmaxf(v3, 0.f);
            }
            float2 w0 = {v0, v1}, w1 = {v2, v3};
            *(float2*)&C[(size_t)r0 * N + c] = w0;
            *(float2*)&C[(size_t)(r0 + 8) * N + c] = w1;
        }
    }
}

// ---------------- softmax over the BATCH axis (axis 0 of [B, N]) ----------------
__global__ __launch_bounds__(256) void softmax_kernel(
    const float* __restrict__ logits, float* __restrict__ out)
{
    const int ncol = blockIdx.x;
    const int t = threadIdx.x;
    __shared__ float red[256];

    float mx = -1e30f;
    for (int bi = t; bi < BB; bi += 256) mx = fmaxf(mx, logits[bi * NN + ncol]);
    red[t] = mx; __syncthreads();
    for (int s = 128; s > 0; s >>= 1) { if (t < s) red[t] = fmaxf(red[t], red[t + s]); __syncthreads(); }
    mx = red[0]; __syncthreads();

    float sum = 0.f;
    for (int bi = t; bi < BB; bi += 256) sum += expf(logits[bi * NN + ncol] - mx);
    red[t] = sum; __syncthreads();
    for (int s = 128; s > 0; s >>= 1) { if (t < s) red[t] += red[t + s]; __syncthreads(); }
    float inv = 1.f / red[0];

    for (int bi = t; bi < BB; bi += 256)
        out[bi * NN + ncol] = expf(logits[bi * NN + ncol] - mx) * inv;
}

// ---------------- launch ----------------
extern "C" void kernel_launch(void* const* d_in, const int* in_sizes, int n_in,
                              void* d_out, int out_size)
{
    const float* x         = (const float*)d_in[0];
    const float* edge_attr = (const float*)d_in[1];
    const float* user_s    = (const float*)d_in[2];
    const float* W_msg     = (const float*)d_in[3];
    const float* b_msg     = (const float*)d_in[4];
    const float* W_edge    = (const float*)d_in[5];
    const float* b_edge    = (const float*)d_in[6];
    const float* W_self    = (const float*)d_in[7];
    const float* b_self    = (const float*)d_in[8];
    const float* W1        = (const float*)d_in[9];
    const float* b1        = (const float*)d_in[10];
    const float* W2        = (const float*)d_in[11];
    const float* b2        = (const float*)d_in[12];
    const float* W3        = (const float*)d_in[13];
    const float* b3        = (const float*)d_in[14];
    const float* W4        = (const float*)d_in[15];
    const float* b4        = (const float*)d_in[16];
    const int*   edge_index = (const int*)d_in[17];
    float* out = (float*)d_out;

    float *states, *h1, *h2, *logits;
    cudaGetSymbolAddress((void**)&states, g_states);
    cudaGetSymbolAddress((void**)&h1, g_h1);
    cudaGetSymbolAddress((void**)&h2, g_h2);
    cudaGetSymbolAddress((void**)&logits, g_logits);

    cudaFuncSetAttribute(tgemm<true>,
                         cudaFuncAttributeMaxDynamicSharedMemorySize, TG_SMEM);
    cudaFuncSetAttribute(tgemm<false>,
                         cudaFuncAttributeMaxDynamicSharedMemorySize, TG_SMEM);

    graph_kernel<<<BB, 256>>>(x, edge_attr, user_s, W_msg, b_msg, W_edge, b_edge,
                              W_self, b_self, W1, b1, edge_index);

    tgemm<true ><<<dim3(HID  / 64, BB / 64), 256, TG_SMEM>>>(states, W2, b2, h1, BB, HID,  SDIM);
    tgemm<true ><<<dim3(HID2 / 64, BB / 64), 256, TG_SMEM>>>(h1,     W3, b3, h2, BB, HID2, HID);
    tgemm<false><<<dim3(NN   / 64, BB / 64), 256, TG_SMEM>>>(h2,     W4, b4, logits, BB, NN, HID2);
    softmax_kernel<<<NN, 256>>>(logits, out);
}

// round 9
// speedup vs baseline: 2.8021x; 1.1285x over previous
#include <cuda_runtime.h>

#define BB 2048
#define NN 64
#define EPG 512
#define TOTAL_N (BB*NN)      // 131072
#define TOTAL_E (BB*EPG)     // 1048576
#define DN 16
#define DE 64
#define DU 32
#define DUE 64
#define HID 512
#define HID2 256
#define SDIM (NN*DE + DUE)   // 4160
#define KSPL 2080            // GEMM1 split-K half (2*2080 = 4160)

// ---------------- scratch (no allocs allowed) ----------------
__device__ float g_states[BB*SDIM];   // 34 MB
__device__ float g_h1p[2*BB*HID];     // split-K partials, 8 MB
__device__ float g_h1[BB*HID];
__device__ float g_h2[BB*HID2];
__device__ float g_logits[BB*NN];

// ---------------- helpers ----------------
__device__ __forceinline__ unsigned s2u(const void* p) {
    return (unsigned)__cvta_generic_to_shared(p);
}

// ---------------- threefry2x32 (JAX, key = PRNGKey(42) = {0,42}) ----------------
__device__ __forceinline__ unsigned int rotl32(unsigned int v, int d) {
    return __funnelshift_l(v, v, d);
}

__device__ __forceinline__ unsigned int threefry_xor(unsigned int x0, unsigned int x1) {
    const unsigned int K0 = 0u, K1 = 42u;
    const unsigned int K2c = 0x1BD11BDAu ^ K0 ^ K1;
#define TF_ROUND(r) { x0 += x1; x1 = rotl32(x1, r); x1 ^= x0; }
    x0 += K0; x1 += K1;
    TF_ROUND(13) TF_ROUND(15) TF_ROUND(26) TF_ROUND(6)
    x0 += K1;  x1 += K2c + 1u;
    TF_ROUND(17) TF_ROUND(29) TF_ROUND(16) TF_ROUND(24)
    x0 += K2c; x1 += K0 + 2u;
    TF_ROUND(13) TF_ROUND(15) TF_ROUND(26) TF_ROUND(6)
    x0 += K0;  x1 += K1 + 3u;
    TF_ROUND(17) TF_ROUND(29) TF_ROUND(16) TF_ROUND(24)
    x0 += K1;  x1 += K2c + 4u;
    TF_ROUND(13) TF_ROUND(15) TF_ROUND(26) TF_ROUND(6)
    x0 += K2c; x1 += K0 + 5u;
#undef TF_ROUND
    return x0 ^ x1;
}

// ---------------- per-graph GNN kernel (x-first aggregation) ----------------
__global__ __launch_bounds__(256) void graph_kernel(
    const float* __restrict__ x, const float* __restrict__ edge_attr,
    const float* __restrict__ user_s,
    const float* __restrict__ W_msg, const float* __restrict__ b_msg,
    const float* __restrict__ W_edge, const float* __restrict__ b_edge,
    const float* __restrict__ W_self, const float* __restrict__ b_self,
    const float* __restrict__ W1, const float* __restrict__ b1,
    const int* __restrict__ edge_index)
{
    __shared__ float sWm[DN][DE];                // 4 KB
    __shared__ float sWs[DN][DE];                // 4 KB
    __shared__ float sWe[2][DE];
    __shared__ float sbme[DE];
    __shared__ float sbs[DE];
    __shared__ __align__(16) float sx[NN][DN];   // 4 KB (rows 64B)
    __shared__ __align__(16) float sxa[NN][DN];  // aggregated x, 4 KB
    __shared__ float sea[NN][2];
    __shared__ int   sedge[EPG];                 // 2 KB
    __shared__ short slist[EPG];                 // 1 KB
    __shared__ int   sdeg[NN];
    __shared__ int   soff[NN];
    __shared__ int   sfill[NN];

    const int b = blockIdx.x;
    const int t = threadIdx.x;

    for (int i = t; i < DN * DE; i += 256) {
        sWm[i / DE][i % DE] = W_msg[i];
        sWs[i / DE][i % DE] = W_self[i];
    }
    for (int i = t; i < 2 * DE; i += 256) sWe[i / DE][i % DE] = W_edge[i];
    if (t < DE) { sbme[t] = b_msg[t] + b_edge[t]; sbs[t] = b_self[t]; }
    for (int i = t; i < NN * DN; i += 256) sx[i / DN][i % DN] = x[b * NN * DN + i];
    if (t < NN) { sdeg[t] = 0; sfill[t] = 0; sea[t][0] = 0.f; sea[t][1] = 0.f; }
    __syncthreads();

    const int n  = t >> 2;           // node 0..63
    const int q  = t & 3;            // 4-float chunk of the 16 node dims
    const int d0 = q * 16;           // 16-wide chunk of the 64 embedding dims

    // pass 1: stash edges, count degrees, aggregate edge attrs at dst
    {
        const int ebase = b * EPG;
        for (int e = t; e < EPG; e += 256) {
            int src = edge_index[ebase + e] - b * NN;
            int dst = edge_index[TOTAL_E + ebase + e] - b * NN;
            sedge[e] = (src << 8) | dst;
            atomicAdd(&sdeg[dst], 1);
            float2 ea = ((const float2*)edge_attr)[ebase + e];
            atomicAdd(&sea[dst][0], ea.x);
            atomicAdd(&sea[dst][1], ea.y);
        }
    }
    __syncthreads();

    // exclusive scan of degrees (warp 0, 2 values/lane)
    if (t < 32) {
        int a = sdeg[2 * t], bv = sdeg[2 * t + 1];
        int s = a + bv;
        int xsc = s;
        #pragma unroll
        for (int d = 1; d < 32; d <<= 1) {
            int y = __shfl_up_sync(0xffffffffu, xsc, d);
            if (t >= d) xsc += y;
        }
        int excl = xsc - s;
        soff[2 * t] = excl;
        soff[2 * t + 1] = excl + a;
    }
    __syncthreads();

    // pass 2: fill CSR lists
    for (int e = t; e < EPG; e += 256) {
        int pk = sedge[e];
        int dst = pk & 0xff;
        int pos = atomicAdd(&sfill[dst], 1);
        slist[soff[dst] + pos] = (short)(pk >> 8);
    }
    __syncthreads();

    // dropout mask bits for this thread's 16 output elements
    unsigned mbits = 0;
    {
        unsigned base_idx = ((unsigned)(b * NN + n) << 6) + d0;
        #pragma unroll 1
        for (int j = 0; j < 16; j++)
            mbits |= (((~threefry_xor(0u, base_idx + j)) >> 31) & 1u) << j;
    }

    // aggregate RAW x over neighbors (16-dim rows: 1 LDS.128 per nbr per thread)
    {
        float4 xa = make_float4(0.f, 0.f, 0.f, 0.f);
        const int cnt = sdeg[n], base = soff[n];
        for (int i = 0; i < cnt; i++) {
            int s = slist[base + i];
            float4 v = ((const float4*)sx[s])[q];
            xa.x += v.x; xa.y += v.y; xa.z += v.z; xa.w += v.w;
        }
        ((float4*)sxa[n])[q] = xa;
    }
    __syncthreads();

    // node = relu(xagg@W_msg + x@W_self + ea@W_edge + deg*(b_msg+b_edge) + b_self)
    {
        float acc[16];
        #pragma unroll
        for (int j = 0; j < 16; j++) acc[j] = sbs[d0 + j];
        #pragma unroll
        for (int k = 0; k < DN; k++) {
            float xv = sx[n][k];
            float av = sxa[n][k];
            #pragma unroll
            for (int j = 0; j < 16; j++)
                acc[j] += xv * sWs[k][d0 + j] + av * sWm[k][d0 + j];
        }
        const float deg = (float)sdeg[n];
        const float e0 = sea[n][0], e1 = sea[n][1];
        #pragma unroll
        for (int j = 0; j < 16; j++) {
            int d = d0 + j;
            float v = acc[j] + e0 * sWe[0][d] + e1 * sWe[1][d] + deg * sbme[d];
            v = (v > 0.f) ? v * 2.f : 0.f;
            if (!((mbits >> j) & 1u)) v = 0.f;
            g_states[b * SDIM + n * DE + d] = v;
        }
    }

    // user embedding: relu(user_s @ W1 + b1) -> states[b][4096:4160]
    if (t < DUE) {
        float acc = b1[t];
        #pragma unroll
        for (int k = 0; k < DU; k++) acc += user_s[b * DU + k] * W1[k * DUE + t];
        g_states[b * SDIM + NN * DE + t] = fmaxf(acc, 0.f);
    }
}

// ---------------- tf32 tensor-core GEMM, cp.async 3-stage pipeline ----------------
// C = act(A[M,K] @ B[K,N] + bias). BMT x 64 x BK32 tiles, 256 thr.
// PARTIAL: split-K partial (blockIdx.z selects K-slab; raw accumulators stored).
__device__ __forceinline__ void mma_tf32(float* d, const uint4& a, unsigned b0, unsigned b1) {
    asm volatile(
        "mma.sync.aligned.m16n8k8.row.col.f32.tf32.tf32.f32 "
        "{%0,%1,%2,%3}, {%4,%5,%6,%7}, {%8,%9}, {%0,%1,%2,%3};"
        : "+f"(d[0]), "+f"(d[1]), "+f"(d[2]), "+f"(d[3])
        : "r"(a.x), "r"(a.y), "r"(a.z), "r"(a.w), "r"(b0), "r"(b1));
}
__device__ __forceinline__ void ldsm4(uint4& r, unsigned addr) {
    asm volatile("ldmatrix.sync.aligned.m8n8.x4.shared.b16 {%0,%1,%2,%3}, [%4];"
                 : "=r"(r.x), "=r"(r.y), "=r"(r.z), "=r"(r.w) : "r"(addr));
}
#define CPA16(dst, src) asm volatile("cp.async.cg.shared.global [%0], [%1], 16;" :: "r"(dst), "l"(src))
#define CPA_COMMIT()    asm volatile("cp.async.commit_group;" ::: "memory")
#define CPA_WAIT1()     asm volatile("cp.async.wait_group 1;" ::: "memory")

#define TG_STG_BF 2304            // floats per B stage (32 rows x 72)

template <int BMT, bool RELU, bool PARTIAL>
__global__ __launch_bounds__(256) void tgemm(
    const float* __restrict__ A, const float* __restrict__ Bw,
    const float* __restrict__ bias, float* __restrict__ C,
    int M, int N, int K, int lda)
{
    constexpr int WN_CNT = (BMT == 64) ? 4 : 2;   // warps along n
    constexpr int NWID   = 64 / WN_CNT;           // warp n-extent (16 or 32)
    constexpr int NT     = NWID / 8;              // n-tiles per warp (2 or 4)
    constexpr int AG     = BMT / 32;              // A cp.async granules per thread
    constexpr int STG_A  = BMT * 128;             // bytes per A stage

    extern __shared__ char smem[];
    float* sB = (float*)(smem + 3 * STG_A);
    const unsigned sAu = s2u(smem);
    const unsigned sBu = s2u(sB);

    if (PARTIAL) {
        A  += (size_t)blockIdx.z * K;             // K = split length
        Bw += (size_t)blockIdx.z * K * N;
        C  += (size_t)blockIdx.z * M * N;
    }

    const int t = threadIdx.x, lane = t & 31, wid = t >> 5;
    const int wm = wid / WN_CNT, wn = wid % WN_CNT;
    const int m0 = blockIdx.y * BMT, n0 = blockIdx.x * 64;

    const int ar0 = t >> 3, ag = t & 7;           // A rows ar0 + 32j
    const int br0 = t >> 4, bg = t & 15;          // B rows br0, br0+16

    int rbA[2], swA[2];
    #pragma unroll
    for (int mt = 0; mt < 2; mt++) {
        int rA = wm * 32 + mt * 16 + (lane & 7) + (((lane >> 3) & 1) << 3);
        rbA[mt] = rA << 7;
        swA[mt] = rA & 7;
    }
    const int csel = lane >> 4;
    const int bkr  = lane & 3;
    const int bnc  = wn * NWID + (lane >> 2);

    float acc[2][NT][4];
    #pragma unroll
    for (int i = 0; i < 2; i++)
        #pragma unroll
        for (int j = 0; j < NT; j++)
            #pragma unroll
            for (int k = 0; k < 4; k++) acc[i][j][k] = 0.f;

    const int nIter = K >> 5;

    #define ISSUE(st, k0)                                                          \
    {                                                                              \
        _Pragma("unroll")                                                          \
        for (int j = 0; j < AG; j++) {                                             \
            int r = ar0 + j * 32;                                                  \
            unsigned d = sAu + (st) * STG_A + (r << 7) + ((ag ^ (r & 7)) << 4);    \
            CPA16(d, A + (size_t)(m0 + r) * lda + (k0) + (ag << 2));               \
        }                                                                          \
        _Pragma("unroll")                                                          \
        for (int j = 0; j < 2; j++) {                                              \
            int r = br0 + j * 16;                                                  \
            unsigned d = sBu + (st) * (TG_STG_BF * 4) + r * 288 + (bg << 4);       \
            CPA16(d, Bw + (size_t)((k0) + r) * N + n0 + (bg << 2));                \
        }                                                                          \
    }

    ISSUE(0, 0); CPA_COMMIT();
    ISSUE(1, 32); CPA_COMMIT();

    for (int it = 0; it < nIter; it++) {
        const int st = it % 3;
        CPA_WAIT1();
        __syncthreads();

        const unsigned aBase = sAu + st * STG_A;
        const float* bBase = sB + st * TG_STG_BF;

        #pragma unroll
        for (int s = 0; s < 4; s++) {
            uint4 af[2];
            #pragma unroll
            for (int mt = 0; mt < 2; mt++) {
                unsigned ad = aBase + rbA[mt] + ((((s << 1) + csel) ^ swA[mt]) << 4);
                ldsm4(af[mt], ad);
            }
            const int kr = (s << 3) + bkr;
            unsigned b0[NT], b1[NT];
            #pragma unroll
            for (int nt = 0; nt < NT; nt++) {
                b0[nt] = __float_as_uint(bBase[kr * 72 + bnc + nt * 8]);
                b1[nt] = __float_as_uint(bBase[(kr + 4) * 72 + bnc + nt * 8]);
            }
            #pragma unroll
            for (int mt = 0; mt < 2; mt++)
                #pragma unroll
                for (int nt = 0; nt < NT; nt++)
                    mma_tf32(acc[mt][nt], af[mt], b0[nt], b1[nt]);
        }

        if (it + 2 < nIter) { const int ns = (it + 2) % 3; ISSUE(ns, (it + 2) << 5); }
        CPA_COMMIT();
    }
    #undef ISSUE

    // epilogue
    #pragma unroll
    for (int mt = 0; mt < 2; mt++) {
        int r0 = m0 + wm * 32 + mt * 16 + (lane >> 2);
        #pragma unroll
        for (int nt = 0; nt < NT; nt++) {
            int c = n0 + wn * NWID + nt * 8 + ((lane & 3) << 1);
            float v0 = acc[mt][nt][0];
            float v1 = acc[mt][nt][1];
            float v2 = acc[mt][nt][2];
            float v3 = acc[mt][nt][3];
            if (!PARTIAL) {
                float bv0 = bias[c], bv1 = bias[c + 1];
                v0 += bv0; v1 += bv1; v2 += bv0; v3 += bv1;
                if (RELU) {
                    v0 = fmaxf(v0, 0.f); v1 = fmaxf(v1, 0.f);
                    v2 = fmaxf(v2, 0.f); v3 = fmaxf(v3, 0.f);
                }
            }
            float2 w0 = {v0, v1}, w1 = {v2, v3};
            *(float2*)&C[(size_t)r0 * N + c] = w0;
            *(float2*)&C[(size_t)(r0 + 8) * N + c] = w1;
        }
    }
}

// ---------------- split-K reduce + bias + relu for GEMM1 ----------------
__global__ __launch_bounds__(256) void reduce_relu(
    const float* __restrict__ p, const float* __restrict__ bias, float* __restrict__ o)
{
    int i = blockIdx.x * 256 + threadIdx.x;          // float4 index
    float4 a = ((const float4*)p)[i];
    float4 b = ((const float4*)p)[i + (BB * HID / 4)];
    int c = (i * 4) & (HID - 1);
    float4 bv = *(const float4*)&bias[c];
    float4 r;
    r.x = fmaxf(a.x + b.x + bv.x, 0.f);
    r.y = fmaxf(a.y + b.y + bv.y, 0.f);
    r.z = fmaxf(a.z + b.z + bv.z, 0.f);
    r.w = fmaxf(a.w + b.w + bv.w, 0.f);
    ((float4*)o)[i] = r;
}

// ---------------- softmax over the BATCH axis (axis 0 of [B, N]) ----------------
__global__ __launch_bounds__(256) void softmax_kernel(
    const float* __restrict__ logits, float* __restrict__ out)
{
    const int ncol = blockIdx.x;
    const int t = threadIdx.x;
    __shared__ float red[256];

    float lv[8];
    #pragma unroll
    for (int r = 0; r < 8; r++) lv[r] = logits[(t + r * 256) * NN + ncol];

    float mx = lv[0];
    #pragma unroll
    for (int r = 1; r < 8; r++) mx = fmaxf(mx, lv[r]);
    red[t] = mx; __syncthreads();
    for (int s = 128; s > 0; s >>= 1) { if (t < s) red[t] = fmaxf(red[t], red[t + s]); __syncthreads(); }
    mx = red[0]; __syncthreads();

    float sum = 0.f;
    #pragma unroll
    for (int r = 0; r < 8; r++) { lv[r] = __expf(lv[r] - mx); sum += lv[r]; }
    red[t] = sum; __syncthreads();
    for (int s = 128; s > 0; s >>= 1) { if (t < s) red[t] += red[t + s]; __syncthreads(); }
    float inv = 1.f / red[0];

    #pragma unroll
    for (int r = 0; r < 8; r++) out[(t + r * 256) * NN + ncol] = lv[r] * inv;
}

// ---------------- launch ----------------
extern "C" void kernel_launch(void* const* d_in, const int* in_sizes, int n_in,
                              void* d_out, int out_size)
{
    const float* x         = (const float*)d_in[0];
    const float* edge_attr = (const float*)d_in[1];
    const float* user_s    = (const float*)d_in[2];
    const float* W_msg     = (const float*)d_in[3];
    const float* b_msg     = (const float*)d_in[4];
    const float* W_edge    = (const float*)d_in[5];
    const float* b_edge    = (const float*)d_in[6];
    const float* W_self    = (const float*)d_in[7];
    const float* b_self    = (const float*)d_in[8];
    const float* W1        = (const float*)d_in[9];
    const float* b1        = (const float*)d_in[10];
    const float* W2        = (const float*)d_in[11];
    const float* b2        = (const float*)d_in[12];
    const float* W3        = (const float*)d_in[13];
    const float* b3        = (const float*)d_in[14];
    const float* W4        = (const float*)d_in[15];
    const float* b4        = (const float*)d_in[16];
    const int*   edge_index = (const int*)d_in[17];
    float* out = (float*)d_out;

    float *states, *h1p, *h1, *h2, *logits;
    cudaGetSymbolAddress((void**)&states, g_states);
    cudaGetSymbolAddress((void**)&h1p, g_h1p);
    cudaGetSymbolAddress((void**)&h1, g_h1);
    cudaGetSymbolAddress((void**)&h2, g_h2);
    cudaGetSymbolAddress((void**)&logits, g_logits);

    const int smem128 = 3 * 128 * 128 + 3 * TG_STG_BF * 4;   // 76800
    const int smem64  = 3 * 64 * 128 + 3 * TG_STG_BF * 4;    // 52224

    cudaFuncSetAttribute(tgemm<128, false, true>,
                         cudaFuncAttributeMaxDynamicSharedMemorySize, smem128);
    cudaFuncSetAttribute(tgemm<64, true, false>,
                         cudaFuncAttributeMaxDynamicSharedMemorySize, smem64);
    cudaFuncSetAttribute(tgemm<64, false, false>,
                         cudaFuncAttributeMaxDynamicSharedMemorySize, smem64);

    graph_kernel<<<BB, 256>>>(x, edge_attr, user_s, W_msg, b_msg, W_edge, b_edge,
                              W_self, b_self, W1, b1, edge_index);

    // GEMM1: split-K=2, BM=128 tiles -> partials, then reduce+bias+relu
    tgemm<128, false, true><<<dim3(HID / 64, BB / 128, 2), 256, smem128>>>(
        states, W2, b2, h1p, BB, HID, KSPL, SDIM);
    reduce_relu<<<BB * HID / 4 / 256, 256>>>(h1p, b2, h1);

    tgemm<64, true , false><<<dim3(HID2 / 64, BB / 64), 256, smem64>>>(
        h1, W3, b3, h2, BB, HID2, HID, HID);
    tgemm<64, false, false><<<dim3(NN / 64, BB / 64), 256, smem64>>>(
        h2, W4, b4, logits, BB, NN, HID2, HID2);
    softmax_kernel<<<NN, 256>>>(logits, out);
}

// round 11
// speedup vs baseline: 3.4389x; 1.2272x over previous
#include <cuda_runtime.h>
#include <cuda_fp16.h>

#define BB 2048
#define NN 64
#define EPG 512
#define TOTAL_N (BB*NN)      // 131072
#define TOTAL_E (BB*EPG)     // 1048576
#define DN 16
#define DE 64
#define DU 32
#define DUE 64
#define HID 512
#define HID2 256
#define SDIM (NN*DE + DUE)   // 4160
#define KSPL 2080            // GEMM1 split-K half (2*2080 = 4160)

// ---------------- scratch (no allocs allowed) ----------------
__device__ __half g_states[BB*SDIM];  // 17 MB (fp16 activations)
__device__ float  g_h1p[2*BB*HID];    // split-K fp32 partials, 8 MB
__device__ __half g_h1[BB*HID];
__device__ __half g_h2[BB*HID2];
__device__ float  g_logits[BB*NN];
__device__ __half g_w2h[SDIM*HID];    // fp16 weights
__device__ __half g_w3h[HID*HID2];
__device__ __half g_w4h[HID2*NN];

// ---------------- helpers ----------------
__device__ __forceinline__ unsigned s2u(const void* p) {
    return (unsigned)__cvta_generic_to_shared(p);
}

// fp32 -> fp16 weight conversion (vectorized, n divisible by 1024)
__global__ __launch_bounds__(256) void cvth(const float* __restrict__ s, __half* __restrict__ d) {
    int i = blockIdx.x * 256 + threadIdx.x;
    float4 v = ((const float4*)s)[i];
    __half2 a = __floats2half2_rn(v.x, v.y);
    __half2 b = __floats2half2_rn(v.z, v.w);
    ((__half2*)d)[2 * i]     = a;
    ((__half2*)d)[2 * i + 1] = b;
}

// ---------------- threefry2x32 (JAX, key = PRNGKey(42) = {0,42}) ----------------
__device__ __forceinline__ unsigned int rotl32(unsigned int v, int d) {
    return __funnelshift_l(v, v, d);
}

__device__ __forceinline__ unsigned int threefry_xor(unsigned int x0, unsigned int x1) {
    const unsigned int K0 = 0u, K1 = 42u;
    const unsigned int K2c = 0x1BD11BDAu ^ K0 ^ K1;
#define TF_ROUND(r) { x0 += x1; x1 = rotl32(x1, r); x1 ^= x0; }
    x0 += K0; x1 += K1;
    TF_ROUND(13) TF_ROUND(15) TF_ROUND(26) TF_ROUND(6)
    x0 += K1;  x1 += K2c + 1u;
    TF_ROUND(17) TF_ROUND(29) TF_ROUND(16) TF_ROUND(24)
    x0 += K2c; x1 += K0 + 2u;
    TF_ROUND(13) TF_ROUND(15) TF_ROUND(26) TF_ROUND(6)
    x0 += K0;  x1 += K1 + 3u;
    TF_ROUND(17) TF_ROUND(29) TF_ROUND(16) TF_ROUND(24)
    x0 += K1;  x1 += K2c + 4u;
    TF_ROUND(13) TF_ROUND(15) TF_ROUND(26) TF_ROUND(6)
    x0 += K2c; x1 += K0 + 5u;
#undef TF_ROUND
    return x0 ^ x1;
}

// ---------------- per-graph GNN kernel (x-first aggregation) ----------------
__global__ __launch_bounds__(256) void graph_kernel(
    const float* __restrict__ x, const float* __restrict__ edge_attr,
    const float* __restrict__ user_s,
    const float* __restrict__ W_msg, const float* __restrict__ b_msg,
    const float* __restrict__ W_edge, const float* __restrict__ b_edge,
    const float* __restrict__ W_self, const float* __restrict__ b_self,
    const float* __restrict__ W1, const float* __restrict__ b1,
    const int* __restrict__ edge_index)
{
    __shared__ float sWm[DN][DE];
    __shared__ float sWs[DN][DE];
    __shared__ float sWe[2][DE];
    __shared__ float sbme[DE];
    __shared__ float sbs[DE];
    __shared__ __align__(16) float sx[NN][DN];
    __shared__ __align__(16) float sxa[NN][DN];
    __shared__ float sea[NN][2];
    __shared__ int   sedge[EPG];
    __shared__ short slist[EPG];
    __shared__ int   sdeg[NN];
    __shared__ int   soff[NN];
    __shared__ int   sfill[NN];

    const int b = blockIdx.x;
    const int t = threadIdx.x;

    for (int i = t; i < DN * DE; i += 256) {
        sWm[i / DE][i % DE] = W_msg[i];
        sWs[i / DE][i % DE] = W_self[i];
    }
    for (int i = t; i < 2 * DE; i += 256) sWe[i / DE][i % DE] = W_edge[i];
    if (t < DE) { sbme[t] = b_msg[t] + b_edge[t]; sbs[t] = b_self[t]; }
    for (int i = t; i < NN * DN; i += 256) sx[i / DN][i % DN] = x[b * NN * DN + i];
    if (t < NN) { sdeg[t] = 0; sfill[t] = 0; sea[t][0] = 0.f; sea[t][1] = 0.f; }
    __syncthreads();

    const int n  = t >> 2;
    const int q  = t & 3;
    const int d0 = q * 16;

    // pass 1: stash edges, count degrees, aggregate edge attrs at dst
    {
        const int ebase = b * EPG;
        for (int e = t; e < EPG; e += 256) {
            int src = edge_index[ebase + e] - b * NN;
            int dst = edge_index[TOTAL_E + ebase + e] - b * NN;
            sedge[e] = (src << 8) | dst;
            atomicAdd(&sdeg[dst], 1);
            float2 ea = ((const float2*)edge_attr)[ebase + e];
            atomicAdd(&sea[dst][0], ea.x);
            atomicAdd(&sea[dst][1], ea.y);
        }
    }
    __syncthreads();

    // exclusive scan of degrees
    if (t < 32) {
        int a = sdeg[2 * t], bv = sdeg[2 * t + 1];
        int s = a + bv;
        int xsc = s;
        #pragma unroll
        for (int d = 1; d < 32; d <<= 1) {
            int y = __shfl_up_sync(0xffffffffu, xsc, d);
            if (t >= d) xsc += y;
        }
        int excl = xsc - s;
        soff[2 * t] = excl;
        soff[2 * t + 1] = excl + a;
    }
    __syncthreads();

    // pass 2: fill CSR lists
    for (int e = t; e < EPG; e += 256) {
        int pk = sedge[e];
        int dst = pk & 0xff;
        int pos = atomicAdd(&sfill[dst], 1);
        slist[soff[dst] + pos] = (short)(pk >> 8);
    }
    __syncthreads();

    // dropout mask bits
    unsigned mbits = 0;
    {
        unsigned base_idx = ((unsigned)(b * NN + n) << 6) + d0;
        #pragma unroll 1
        for (int j = 0; j < 16; j++)
            mbits |= (((~threefry_xor(0u, base_idx + j)) >> 31) & 1u) << j;
    }

    // aggregate RAW x over neighbors
    {
        float4 xa = make_float4(0.f, 0.f, 0.f, 0.f);
        const int cnt = sdeg[n], base = soff[n];
        for (int i = 0; i < cnt; i++) {
            int s = slist[base + i];
            float4 v = ((const float4*)sx[s])[q];
            xa.x += v.x; xa.y += v.y; xa.z += v.z; xa.w += v.w;
        }
        ((float4*)sxa[n])[q] = xa;
    }
    __syncthreads();

    // node = relu(xagg@W_msg + x@W_self + ea@W_edge + deg*(b_msg+b_edge) + b_self)
    {
        float acc[16];
        #pragma unroll
        for (int j = 0; j < 16; j++) acc[j] = sbs[d0 + j];
        #pragma unroll
        for (int k = 0; k < DN; k++) {
            float xv = sx[n][k];
            float av = sxa[n][k];
            #pragma unroll
            for (int j = 0; j < 16; j++)
                acc[j] += xv * sWs[k][d0 + j] + av * sWm[k][d0 + j];
        }
        const float deg = (float)sdeg[n];
        const float e0 = sea[n][0], e1 = sea[n][1];
        float v[16];
        #pragma unroll
        for (int j = 0; j < 16; j++) {
            int d = d0 + j;
            float u = acc[j] + e0 * sWe[0][d] + e1 * sWe[1][d] + deg * sbme[d];
            u = (u > 0.f) ? u * 2.f : 0.f;
            if (!((mbits >> j) & 1u)) u = 0.f;
            v[j] = u;
        }
        #pragma unroll
        for (int j = 0; j < 16; j += 2) {
            __half2 h = __floats2half2_rn(v[j], v[j + 1]);
            *(__half2*)&g_states[b * SDIM + n * DE + d0 + j] = h;
        }
    }

    // user embedding
    if (t < DUE) {
        float acc = b1[t];
        #pragma unroll
        for (int k = 0; k < DU; k++) acc += user_s[b * DU + k] * W1[k * DUE + t];
        g_states[b * SDIM + NN * DE + t] = __float2half_rn(fmaxf(acc, 0.f));
    }
}

// ---------------- fp16 tensor-core GEMM, cp.async 3-stage pipeline ----------------
// C = act(A[M,K] @ B[K,N] + bias). BMT x 64 x BK32 (halves), 256 thr.
__device__ __forceinline__ void mma_f16(float* d, const uint4& a, unsigned b0, unsigned b1) {
    asm volatile(
        "mma.sync.aligned.m16n8k16.row.col.f32.f16.f16.f32 "
        "{%0,%1,%2,%3}, {%4,%5,%6,%7}, {%8,%9}, {%0,%1,%2,%3};"
        : "+f"(d[0]), "+f"(d[1]), "+f"(d[2]), "+f"(d[3])
        : "r"(a.x), "r"(a.y), "r"(a.z), "r"(a.w), "r"(b0), "r"(b1));
}
__device__ __forceinline__ void ldsm4(uint4& r, unsigned addr) {
    asm volatile("ldmatrix.sync.aligned.m8n8.x4.shared.b16 {%0,%1,%2,%3}, [%4];"
                 : "=r"(r.x), "=r"(r.y), "=r"(r.z), "=r"(r.w) : "r"(addr));
}
__device__ __forceinline__ void ldsm4t(uint4& r, unsigned addr) {
    asm volatile("ldmatrix.sync.aligned.m8n8.x4.trans.shared.b16 {%0,%1,%2,%3}, [%4];"
                 : "=r"(r.x), "=r"(r.y), "=r"(r.z), "=r"(r.w) : "r"(addr));
}
#define CPA16(dst, src) asm volatile("cp.async.cg.shared.global [%0], [%1], 16;" :: "r"(dst), "l"(src))
#define CPA_COMMIT()    asm volatile("cp.async.commit_group;" ::: "memory")
#define CPA_WAIT1()     asm volatile("cp.async.wait_group 1;" ::: "memory")

// A stage: BMT rows x 32 halves (64B) padded to 80B/row  -> conflict-free ldsm
// B stage: 32 k-rows x 64 halves (128B) padded to 144B/row -> conflict-free ldsm.trans
#define HSTG_B 4608

template <int BMT, bool PARTIAL, bool RELU, typename OutT>
__global__ __launch_bounds__(256) void hgemm(
    const __half* __restrict__ A, const __half* __restrict__ Bw,
    const float* __restrict__ bias, OutT* __restrict__ C,
    int M, int N, int K, int lda)
{
    constexpr int WN_CNT = (BMT == 64) ? 4 : 2;
    constexpr int NWID   = 64 / WN_CNT;      // 16 or 32
    constexpr int NT     = NWID / 8;         // 2 or 4
    constexpr int AG     = BMT / 64;         // A granule loops per thread
    constexpr int STG_A  = BMT * 80;

    extern __shared__ char smem[];
    const unsigned sAu = s2u(smem);
    const unsigned sBu = sAu + 3 * STG_A;

    if (PARTIAL) {
        A  += (size_t)blockIdx.z * K;
        Bw += (size_t)blockIdx.z * K * N;
        C  += (size_t)blockIdx.z * M * N;
    }

    const int t = threadIdx.x, lane = t & 31, wid = t >> 5;
    const int wm = wid / WN_CNT, wn = wid % WN_CNT;
    const int m0 = blockIdx.y * BMT, n0 = blockIdx.x * 64;

    // cp.async coords
    const int ar = t >> 2, agc = t & 3;      // A: rows ar + 64j, 16B granule agc
    const int br = t >> 3, bg = t & 7;       // B: k-row br, granule bg

    // ldmatrix A offsets (per m-tile)
    int aoff[2];
    #pragma unroll
    for (int mt = 0; mt < 2; mt++) {
        int row = wm * 32 + mt * 16 + (lane & 7) + (((lane >> 3) & 1) << 3);
        aoff[mt] = row * 80 + (((lane >> 4) & 1) << 4);
    }
    // ldmatrix B offsets (per 16-wide n group)
    int boff[NT / 2];
    #pragma unroll
    for (int n2 = 0; n2 < NT / 2; n2++) {
        int krow = (lane & 7) + (((lane >> 3) & 1) << 3);
        int ncol = wn * NWID + n2 * 16 + (((lane >> 4) & 1) << 3);
        boff[n2] = krow * 144 + ncol * 2;
    }

    float acc[2][NT][4];
    #pragma unroll
    for (int i = 0; i < 2; i++)
        #pragma unroll
        for (int j = 0; j < NT; j++)
            #pragma unroll
            for (int k = 0; k < 4; k++) acc[i][j][k] = 0.f;

    const int nIter = K >> 5;

    #define ISSUE(st, k0)                                                         \
    {                                                                             \
        _Pragma("unroll")                                                         \
        for (int j = 0; j < AG; j++) {                                            \
            int r = ar + 64 * j;                                                  \
            unsigned d = sAu + (st) * STG_A + r * 80 + (agc << 4);                \
            CPA16(d, A + (size_t)(m0 + r) * lda + (k0) + (agc << 3));             \
        }                                                                         \
        {                                                                         \
            unsigned d = sBu + (st) * HSTG_B + br * 144 + (bg << 4);              \
            CPA16(d, Bw + (size_t)((k0) + br) * N + n0 + (bg << 3));              \
        }                                                                         \
    }

    ISSUE(0, 0); CPA_COMMIT();
    ISSUE(1, 32); CPA_COMMIT();

    for (int it = 0; it < nIter; it++) {
        const int st = it % 3;
        CPA_WAIT1();
        __syncthreads();

        const unsigned aBase = sAu + st * STG_A;
        const unsigned bBase = sBu + st * HSTG_B;

        #pragma unroll
        for (int ks = 0; ks < 2; ks++) {
            uint4 af[2];
            #pragma unroll
            for (int mt = 0; mt < 2; mt++)
                ldsm4(af[mt], aBase + aoff[mt] + (ks << 5));
            uint4 bf[NT / 2];
            #pragma unroll
            for (int n2 = 0; n2 < NT / 2; n2++)
                ldsm4t(bf[n2], bBase + ks * 2304 + boff[n2]);
            #pragma unroll
            for (int mt = 0; mt < 2; mt++)
                #pragma unroll
                for (int nt = 0; nt < NT; nt++) {
                    unsigned bb0 = (nt & 1) ? bf[nt >> 1].z : bf[nt >> 1].x;
                    unsigned bb1 = (nt & 1) ? bf[nt >> 1].w : bf[nt >> 1].y;
                    mma_f16(acc[mt][nt], af[mt], bb0, bb1);
                }
        }

        if (it + 2 < nIter) { const int ns = (it + 2) % 3; ISSUE(ns, (it + 2) << 5); }
        CPA_COMMIT();
    }
    #undef ISSUE

    // epilogue
    #pragma unroll
    for (int mt = 0; mt < 2; mt++) {
        int r0 = m0 + wm * 32 + mt * 16 + (lane >> 2);
        #pragma unroll
        for (int nt = 0; nt < NT; nt++) {
            int c = n0 + wn * NWID + nt * 8 + ((lane & 3) << 1);
            float v0 = acc[mt][nt][0];
            float v1 = acc[mt][nt][1];
            float v2 = acc[mt][nt][2];
            float v3 = acc[mt][nt][3];
            if (PARTIAL) {
                // raw fp32 partials
                *(float2*)&((float*)C)[(size_t)r0 * N + c]       = make_float2(v0, v1);
                *(float2*)&((float*)C)[(size_t)(r0 + 8) * N + c] = make_float2(v2, v3);
            } else {
                float bv0 = bias[c], bv1 = bias[c + 1];
                v0 += bv0; v1 += bv1; v2 += bv0; v3 += bv1;
                if (RELU) {
                    v0 = fmaxf(v0, 0.f); v1 = fmaxf(v1, 0.f);
                    v2 = fmaxf(v2, 0.f); v3 = fmaxf(v3, 0.f);
                }
                if (sizeof(OutT) == 2) {
                    *(__half2*)&((__half*)C)[(size_t)r0 * N + c]       = __floats2half2_rn(v0, v1);
                    *(__half2*)&((__half*)C)[(size_t)(r0 + 8) * N + c] = __floats2half2_rn(v2, v3);
                } else {
                    *(float2*)&((float*)C)[(size_t)r0 * N + c]       = make_float2(v0, v1);
                    *(float2*)&((float*)C)[(size_t)(r0 + 8) * N + c] = make_float2(v2, v3);
                }
            }
        }
    }
}

// ---------------- split-K reduce + bias + relu -> fp16 h1 ----------------
__global__ __launch_bounds__(256) void reduce_relu(
    const float* __restrict__ p, const float* __restrict__ bias, __half* __restrict__ o)
{
    int i = blockIdx.x * 256 + threadIdx.x;          // float4 index
    float4 a = ((const float4*)p)[i];
    float4 b = ((const float4*)p)[i + (BB * HID / 4)];
    int c = (i * 4) & (HID - 1);
    float4 bv = *(const float4*)&bias[c];
    __half2 r0 = __floats2half2_rn(fmaxf(a.x + b.x + bv.x, 0.f), fmaxf(a.y + b.y + bv.y, 0.f));
    __half2 r1 = __floats2half2_rn(fmaxf(a.z + b.z + bv.z, 0.f), fmaxf(a.w + b.w + bv.w, 0.f));
    ((__half2*)o)[2 * i]     = r0;
    ((__half2*)o)[2 * i + 1] = r1;
}

// ---------------- softmax over the BATCH axis ----------------
__global__ __launch_bounds__(256) void softmax_kernel(
    const float* __restrict__ logits, float* __restrict__ out)
{
    const int ncol = blockIdx.x;
    const int t = threadIdx.x;
    __shared__ float red[256];

    float lv[8];
    #pragma unroll
    for (int r = 0; r < 8; r++) lv[r] = logits[(t + r * 256) * NN + ncol];

    float mx = lv[0];
    #pragma unroll
    for (int r = 1; r < 8; r++) mx = fmaxf(mx, lv[r]);
    red[t] = mx; __syncthreads();
    for (int s = 128; s > 0; s >>= 1) { if (t < s) red[t] = fmaxf(red[t], red[t + s]); __syncthreads(); }
    mx = red[0]; __syncthreads();

    float sum = 0.f;
    #pragma unroll
    for (int r = 0; r < 8; r++) { lv[r] = __expf(lv[r] - mx); sum += lv[r]; }
    red[t] = sum; __syncthreads();
    for (int s = 128; s > 0; s >>= 1) { if (t < s) red[t] += red[t + s]; __syncthreads(); }
    float inv = 1.f / red[0];

    #pragma unroll
    for (int r = 0; r < 8; r++) out[(t + r * 256) * NN + ncol] = lv[r] * inv;
}

// ---------------- launch ----------------
extern "C" void kernel_launch(void* const* d_in, const int* in_sizes, int n_in,
                              void* d_out, int out_size)
{
    const float* x         = (const float*)d_in[0];
    const float* edge_attr = (const float*)d_in[1];
    const float* user_s    = (const float*)d_in[2];
    const float* W_msg     = (const float*)d_in[3];
    const float* b_msg     = (const float*)d_in[4];
    const float* W_edge    = (const float*)d_in[5];
    const float* b_edge    = (const float*)d_in[6];
    const float* W_self    = (const float*)d_in[7];
    const float* b_self    = (const float*)d_in[8];
    const float* W1        = (const float*)d_in[9];
    const float* b1        = (const float*)d_in[10];
    const float* W2        = (const float*)d_in[11];
    const float* b2        = (const float*)d_in[12];
    const float* W3        = (const float*)d_in[13];
    const float* b3        = (const float*)d_in[14];
    const float* W4        = (const float*)d_in[15];
    const float* b4        = (const float*)d_in[16];
    const int*   edge_index = (const int*)d_in[17];
    float* out = (float*)d_out;

    __half *states, *h1, *h2, *w2h, *w3h, *w4h;
    float *h1p, *logits;
    cudaGetSymbolAddress((void**)&states, g_states);
    cudaGetSymbolAddress((void**)&h1p, g_h1p);
    cudaGetSymbolAddress((void**)&h1, g_h1);
    cudaGetSymbolAddress((void**)&h2, g_h2);
    cudaGetSymbolAddress((void**)&logits, g_logits);
    cudaGetSymbolAddress((void**)&w2h, g_w2h);
    cudaGetSymbolAddress((void**)&w3h, g_w3h);
    cudaGetSymbolAddress((void**)&w4h, g_w4h);

    const int smem128 = 3 * (128 * 80 + HSTG_B);   // 44544
    const int smem64  = 3 * (64 * 80 + HSTG_B);    // 29184

    cudaFuncSetAttribute((const void*)hgemm<128, true, false, float>,
                         cudaFuncAttributeMaxDynamicSharedMemorySize, smem128);
    cudaFuncSetAttribute((const void*)hgemm<64, false, true, __half>,
                         cudaFuncAttributeMaxDynamicSharedMemorySize, smem64);
    cudaFuncSetAttribute((const void*)hgemm<64, false, false, float>,
                         cudaFuncAttributeMaxDynamicSharedMemorySize, smem64);

    // weight conversion (every call; cheap, deterministic)
    cvth<<<SDIM * HID / 1024, 256>>>(W2, w2h);
    cvth<<<HID * HID2 / 1024, 256>>>(W3, w3h);
    cvth<<<HID2 * NN / 1024, 256>>>(W4, w4h);

    graph_kernel<<<BB, 256>>>(x, edge_attr, user_s, W_msg, b_msg, W_edge, b_edge,
                              W_self, b_self, W1, b1, edge_index);

    // GEMM1: fp16, split-K=2, BM=128 -> fp32 partials, then reduce+bias+relu -> fp16
    hgemm<128, true, false, float><<<dim3(HID / 64, BB / 128, 2), 256, smem128>>>(
        states, w2h, b2, h1p, BB, HID, KSPL, SDIM);
    reduce_relu<<<BB * HID / 4 / 256, 256>>>(h1p, b2, h1);

    hgemm<64, false, true, __half><<<dim3(HID2 / 64, BB / 64), 256, smem64>>>(
        h1, w3h, b3, h2, BB, HID2, HID, HID);
    hgemm<64, false, false, float><<<dim3(NN / 64, BB / 64), 256, smem64>>>(
        h2, w4h, b4, logits, BB, NN, HID2, HID2);
    softmax_kernel<<<NN, 256>>>(logits, out);
}

// round 12
// speedup vs baseline: 3.7647x; 1.0947x over previous
#include <cuda_runtime.h>
#include <cuda_fp16.h>

#define BB 2048
#define NN 64
#define EPG 512
#define TOTAL_N (BB*NN)      // 131072
#define TOTAL_E (BB*EPG)     // 1048576
#define DN 16
#define DE 64
#define DU 32
#define DUE 64
#define HID 512
#define HID2 256
#define SDIM (NN*DE + DUE)   // 4160
#define KSPL 2080            // GEMM1 split-K half
#define KSPL3 128            // GEMM3 split-K half (2*128 = 256)

// ---------------- scratch (no allocs allowed) ----------------
__device__ __half g_states[BB*SDIM];
__device__ float  g_h1p[2*BB*HID];
__device__ __half g_h1[BB*HID];
__device__ __half g_h2[BB*HID2];
__device__ float  g_lp[2*BB*NN];
__device__ float  g_logits[BB*NN];
__device__ __half g_w2h[SDIM*HID];
__device__ __half g_w3h[HID*HID2];
__device__ __half g_w4h[HID2*NN];

// ---------------- helpers ----------------
__device__ __forceinline__ unsigned s2u(const void* p) {
    return (unsigned)__cvta_generic_to_shared(p);
}

__global__ __launch_bounds__(256) void cvth(const float* __restrict__ s, __half* __restrict__ d) {
    int i = blockIdx.x * 256 + threadIdx.x;
    float4 v = ((const float4*)s)[i];
    ((__half2*)d)[2 * i]     = __floats2half2_rn(v.x, v.y);
    ((__half2*)d)[2 * i + 1] = __floats2half2_rn(v.z, v.w);
}

// ---------------- threefry2x32 (JAX, key = PRNGKey(42) = {0,42}) ----------------
__device__ __forceinline__ unsigned int rotl32(unsigned int v, int d) {
    return __funnelshift_l(v, v, d);
}

__device__ __forceinline__ unsigned int threefry_xor(unsigned int x0, unsigned int x1) {
    const unsigned int K0 = 0u, K1 = 42u;
    const unsigned int K2c = 0x1BD11BDAu ^ K0 ^ K1;
#define TF_ROUND(r) { x0 += x1; x1 = rotl32(x1, r); x1 ^= x0; }
    x0 += K0; x1 += K1;
    TF_ROUND(13) TF_ROUND(15) TF_ROUND(26) TF_ROUND(6)
    x0 += K1;  x1 += K2c + 1u;
    TF_ROUND(17) TF_ROUND(29) TF_ROUND(16) TF_ROUND(24)
    x0 += K2c; x1 += K0 + 2u;
    TF_ROUND(13) TF_ROUND(15) TF_ROUND(26) TF_ROUND(6)
    x0 += K0;  x1 += K1 + 3u;
    TF_ROUND(17) TF_ROUND(29) TF_ROUND(16) TF_ROUND(24)
    x0 += K1;  x1 += K2c + 4u;
    TF_ROUND(13) TF_ROUND(15) TF_ROUND(26) TF_ROUND(6)
    x0 += K2c; x1 += K0 + 5u;
#undef TF_ROUND
    return x0 ^ x1;
}

// ---------------- per-graph GNN kernel ----------------
// Padded per-node edge lists via atomic slot return; no scan, no second pass.
__global__ __launch_bounds__(256) void graph_kernel(
    const float* __restrict__ x, const float* __restrict__ edge_attr,
    const float* __restrict__ user_s,
    const float* __restrict__ W_msg, const float* __restrict__ b_msg,
    const float* __restrict__ W_edge, const float* __restrict__ b_edge,
    const float* __restrict__ W_self, const float* __restrict__ b_self,
    const float* __restrict__ W1, const float* __restrict__ b1,
    const int* __restrict__ edge_index)
{
    __shared__ float sWm[DN][DE];                   // 4 KB
    __shared__ float sWs[DN][DE];                   // 4 KB
    __shared__ float sWe[2][DE];
    __shared__ float sbme[DE];
    __shared__ float sbs[DE];
    __shared__ __align__(16) float sx[NN][20];      // 5 KB (80B rows: conflict-free gather)
    __shared__ __align__(16) float sxa[NN][20];     // 5 KB
    __shared__ float2 sead[EPG];                    // 4 KB staged edge_attr
    __shared__ unsigned short slist[NN * 32];       // 4 KB padded lists: (e<<6)|src
    __shared__ int sdeg[NN];

    const int b = blockIdx.x;
    const int t = threadIdx.x;

    for (int i = t; i < DN * DE; i += 256) {
        sWm[i / DE][i % DE] = W_msg[i];
        sWs[i / DE][i % DE] = W_self[i];
    }
    for (int i = t; i < 2 * DE; i += 256) sWe[i / DE][i % DE] = W_edge[i];
    if (t < DE) { sbme[t] = b_msg[t] + b_edge[t]; sbs[t] = b_self[t]; }
    for (int i = t; i < NN * DN; i += 256) sx[i / DN][i % DN] = x[b * NN * DN + i];
    if (t < NN) sdeg[t] = 0;
    __syncthreads();

    const int n  = t >> 2;
    const int q  = t & 3;
    const int d0 = q * 16;

    // pass 1: one atomic per edge; slot index = returned count
    {
        const int ebase = b * EPG;
        for (int e = t; e < EPG; e += 256) {
            int src = edge_index[ebase + e] - b * NN;
            int dst = edge_index[TOTAL_E + ebase + e] - b * NN;
            int slot = atomicAdd(&sdeg[dst], 1);
            slist[(dst << 5) + slot] = (unsigned short)((e << 6) | src);
            sead[e] = ((const float2*)edge_attr)[ebase + e];
        }
    }

    // dropout mask bits (overlaps with atomic latency before the barrier)
    unsigned mbits = 0;
    {
        unsigned base_idx = ((unsigned)(b * NN + n) << 6) + d0;
        #pragma unroll 1
        for (int j = 0; j < 16; j++)
            mbits |= (((~threefry_xor(0u, base_idx + j)) >> 31) & 1u) << j;
    }
    __syncthreads();

    // gather: sum raw x over neighbors + edge attrs (ea read is 4-lane broadcast)
    const int cnt = sdeg[n];
    float e0 = 0.f, e1 = 0.f;
    {
        float4 xa = make_float4(0.f, 0.f, 0.f, 0.f);
        const int lbase = n << 5;
        for (int i = 0; i < cnt; i++) {
            unsigned v = slist[lbase + i];
            int s = v & 63;
            float4 xv = *(const float4*)&sx[s][q * 4];
            xa.x += xv.x; xa.y += xv.y; xa.z += xv.z; xa.w += xv.w;
            float2 ea = sead[v >> 6];
            e0 += ea.x; e1 += ea.y;
        }
        *(float4*)&sxa[n][q * 4] = xa;
    }
    __syncthreads();

    // node = relu(xagg@W_msg + x@W_self + ea@W_edge + deg*(b_msg+b_edge) + b_self)
    {
        float acc[16];
        #pragma unroll
        for (int j = 0; j < 16; j++) acc[j] = sbs[d0 + j];
        #pragma unroll
        for (int k = 0; k < DN; k++) {
            float xv = sx[n][k];
            float av = sxa[n][k];
            #pragma unroll
            for (int j = 0; j < 16; j++)
                acc[j] += xv * sWs[k][d0 + j] + av * sWm[k][d0 + j];
        }
        const float deg = (float)cnt;
        float v[16];
        #pragma unroll
        for (int j = 0; j < 16; j++) {
            int d = d0 + j;
            float u = acc[j] + e0 * sWe[0][d] + e1 * sWe[1][d] + deg * sbme[d];
            u = (u > 0.f) ? u * 2.f : 0.f;
            if (!((mbits >> j) & 1u)) u = 0.f;
            v[j] = u;
        }
        #pragma unroll
        for (int j = 0; j < 16; j += 2)
            *(__half2*)&g_states[b * SDIM + n * DE + d0 + j] = __floats2half2_rn(v[j], v[j + 1]);
    }

    // user embedding
    if (t < DUE) {
        float acc = b1[t];
        #pragma unroll
        for (int k = 0; k < DU; k++) acc += user_s[b * DU + k] * W1[k * DUE + t];
        g_states[b * SDIM + NN * DE + t] = __float2half_rn(fmaxf(acc, 0.f));
    }
}

// ---------------- fp16 tensor-core GEMM, cp.async 3-stage pipeline ----------------
__device__ __forceinline__ void mma_f16(float* d, const uint4& a, unsigned b0, unsigned b1) {
    asm volatile(
        "mma.sync.aligned.m16n8k16.row.col.f32.f16.f16.f32 "
        "{%0,%1,%2,%3}, {%4,%5,%6,%7}, {%8,%9}, {%0,%1,%2,%3};"
        : "+f"(d[0]), "+f"(d[1]), "+f"(d[2]), "+f"(d[3])
        : "r"(a.x), "r"(a.y), "r"(a.z), "r"(a.w), "r"(b0), "r"(b1));
}
__device__ __forceinline__ void ldsm4(uint4& r, unsigned addr) {
    asm volatile("ldmatrix.sync.aligned.m8n8.x4.shared.b16 {%0,%1,%2,%3}, [%4];"
                 : "=r"(r.x), "=r"(r.y), "=r"(r.z), "=r"(r.w) : "r"(addr));
}
__device__ __forceinline__ void ldsm4t(uint4& r, unsigned addr) {
    asm volatile("ldmatrix.sync.aligned.m8n8.x4.trans.shared.b16 {%0,%1,%2,%3}, [%4];"
                 : "=r"(r.x), "=r"(r.y), "=r"(r.z), "=r"(r.w) : "r"(addr));
}
#define CPA16(dst, src) asm volatile("cp.async.cg.shared.global [%0], [%1], 16;" :: "r"(dst), "l"(src))
#define CPA_COMMIT()    asm volatile("cp.async.commit_group;" ::: "memory")
#define CPA_WAIT1()     asm volatile("cp.async.wait_group 1;" ::: "memory")

#define HSTG_B 4608

template <int BMT, bool PARTIAL, bool RELU, typename OutT>
__global__ __launch_bounds__(256) void hgemm(
    const __half* __restrict__ A, const __half* __restrict__ Bw,
    const float* __restrict__ bias, OutT* __restrict__ C,
    int M, int N, int K, int lda)
{
    constexpr int WN_CNT = (BMT == 64) ? 4 : 2;
    constexpr int NWID   = 64 / WN_CNT;
    constexpr int NT     = NWID / 8;
    constexpr int AG     = BMT / 64;
    constexpr int STG_A  = BMT * 80;

    extern __shared__ char smem[];
    const unsigned sAu = s2u(smem);
    const unsigned sBu = sAu + 3 * STG_A;

    if (PARTIAL) {
        A  += (size_t)blockIdx.z * K;
        Bw += (size_t)blockIdx.z * K * N;
        C  += (size_t)blockIdx.z * M * N;
    }

    const int t = threadIdx.x, lane = t & 31, wid = t >> 5;
    const int wm = wid / WN_CNT, wn = wid % WN_CNT;
    const int m0 = blockIdx.y * BMT, n0 = blockIdx.x * 64;

    const int ar = t >> 2, agc = t & 3;
    const int br = t >> 3, bg = t & 7;

    int aoff[2];
    #pragma unroll
    for (int mt = 0; mt < 2; mt++) {
        int row = wm * 32 + mt * 16 + (lane & 7) + (((lane >> 3) & 1) << 3);
        aoff[mt] = row * 80 + (((lane >> 4) & 1) << 4);
    }
    int boff[NT / 2];
    #pragma unroll
    for (int n2 = 0; n2 < NT / 2; n2++) {
        int krow = (lane & 7) + (((lane >> 3) & 1) << 3);
        int ncol = wn * NWID + n2 * 16 + (((lane >> 4) & 1) << 3);
        boff[n2] = krow * 144 + ncol * 2;
    }

    float acc[2][NT][4];
    #pragma unroll
    for (int i = 0; i < 2; i++)
        #pragma unroll
        for (int j = 0; j < NT; j++)
            #pragma unroll
            for (int k = 0; k < 4; k++) acc[i][j][k] = 0.f;

    const int nIter = K >> 5;

    #define ISSUE(st, k0)                                                         \
    {                                                                             \
        _Pragma("unroll")                                                         \
        for (int j = 0; j < AG; j++) {                                            \
            int r = ar + 64 * j;                                                  \
            unsigned d = sAu + (st) * STG_A + r * 80 + (agc << 4);                \
            CPA16(d, A + (size_t)(m0 + r) * lda + (k0) + (agc << 3));             \
        }                                                                         \
        {                                                                         \
            unsigned d = sBu + (st) * HSTG_B + br * 144 + (bg << 4);              \
            CPA16(d, Bw + (size_t)((k0) + br) * N + n0 + (bg << 3));              \
        }                                                                         \
    }

    ISSUE(0, 0); CPA_COMMIT();
    ISSUE(1, 32); CPA_COMMIT();

    for (int it = 0; it < nIter; it++) {
        const int st = it % 3;
        CPA_WAIT1();
        __syncthreads();

        const unsigned aBase = sAu + st * STG_A;
        const unsigned bBase = sBu + st * HSTG_B;

        #pragma unroll
        for (int ks = 0; ks < 2; ks++) {
            uint4 af[2];
            #pragma unroll
            for (int mt = 0; mt < 2; mt++)
                ldsm4(af[mt], aBase + aoff[mt] + (ks << 5));
            uint4 bf[NT / 2];
            #pragma unroll
            for (int n2 = 0; n2 < NT / 2; n2++)
                ldsm4t(bf[n2], bBase + ks * 2304 + boff[n2]);
            #pragma unroll
            for (int mt = 0; mt < 2; mt++)
                #pragma unroll
                for (int nt = 0; nt < NT; nt++) {
                    unsigned bb0 = (nt & 1) ? bf[nt >> 1].z : bf[nt >> 1].x;
                    unsigned bb1 = (nt & 1) ? bf[nt >> 1].w : bf[nt >> 1].y;
                    mma_f16(acc[mt][nt], af[mt], bb0, bb1);
                }
        }

        if (it + 2 < nIter) { const int ns = (it + 2) % 3; ISSUE(ns, (it + 2) << 5); }
        CPA_COMMIT();
    }
    #undef ISSUE

    #pragma unroll
    for (int mt = 0; mt < 2; mt++) {
        int r0 = m0 + wm * 32 + mt * 16 + (lane >> 2);
        #pragma unroll
        for (int nt = 0; nt < NT; nt++) {
            int c = n0 + wn * NWID + nt * 8 + ((lane & 3) << 1);
            float v0 = acc[mt][nt][0];
            float v1 = acc[mt][nt][1];
            float v2 = acc[mt][nt][2];
            float v3 = acc[mt][nt][3];
            if (PARTIAL) {
                *(float2*)&((float*)C)[(size_t)r0 * N + c]       = make_float2(v0, v1);
                *(float2*)&((float*)C)[(size_t)(r0 + 8) * N + c] = make_float2(v2, v3);
            } else {
                float bv0 = bias[c], bv1 = bias[c + 1];
                v0 += bv0; v1 += bv1; v2 += bv0; v3 += bv1;
                if (RELU) {
                    v0 = fmaxf(v0, 0.f); v1 = fmaxf(v1, 0.f);
                    v2 = fmaxf(v2, 0.f); v3 = fmaxf(v3, 0.f);
                }
                if (sizeof(OutT) == 2) {
                    *(__half2*)&((__half*)C)[(size_t)r0 * N + c]       = __floats2half2_rn(v0, v1);
                    *(__half2*)&((__half*)C)[(size_t)(r0 + 8) * N + c] = __floats2half2_rn(v2, v3);
                } else {
                    *(float2*)&((float*)C)[(size_t)r0 * N + c]       = make_float2(v0, v1);
                    *(float2*)&((float*)C)[(size_t)(r0 + 8) * N + c] = make_float2(v2, v3);
                }
            }
        }
    }
}

// ---------------- split-K reduces ----------------
__global__ __launch_bounds__(256) void reduce_relu(
    const float* __restrict__ p, const float* __restrict__ bias, __half* __restrict__ o)
{
    int i = blockIdx.x * 256 + threadIdx.x;
    float4 a = ((const float4*)p)[i];
    float4 b = ((const float4*)p)[i + (BB * HID / 4)];
    int c = (i * 4) & (HID - 1);
    float4 bv = *(const float4*)&bias[c];
    __half2 r0 = __floats2half2_rn(fmaxf(a.x + b.x + bv.x, 0.f), fmaxf(a.y + b.y + bv.y, 0.f));
    __half2 r1 = __floats2half2_rn(fmaxf(a.z + b.z + bv.z, 0.f), fmaxf(a.w + b.w + bv.w, 0.f));
    ((__half2*)o)[2 * i]     = r0;
    ((__half2*)o)[2 * i + 1] = r1;
}

__global__ __launch_bounds__(256) void reduce_logits(
    const float* __restrict__ p, const float* __restrict__ bias, float* __restrict__ o)
{
    int i = blockIdx.x * 256 + threadIdx.x;
    float4 a = ((const float4*)p)[i];
    float4 b = ((const float4*)p)[i + (BB * NN / 4)];
    int c = (i * 4) & (NN - 1);
    float4 bv = *(const float4*)&bias[c];
    float4 r;
    r.x = a.x + b.x + bv.x; r.y = a.y + b.y + bv.y;
    r.z = a.z + b.z + bv.z; r.w = a.w + b.w + bv.w;
    ((float4*)o)[i] = r;
}

// ---------------- softmax over the BATCH axis ----------------
__global__ __launch_bounds__(256) void softmax_kernel(
    const float* __restrict__ logits, float* __restrict__ out)
{
    const int ncol = blockIdx.x;
    const int t = threadIdx.x;
    __shared__ float red[256];

    float lv[8];
    #pragma unroll
    for (int r = 0; r < 8; r++) lv[r] = logits[(t + r * 256) * NN + ncol];

    float mx = lv[0];
    #pragma unroll
    for (int r = 1; r < 8; r++) mx = fmaxf(mx, lv[r]);
    red[t] = mx; __syncthreads();
    for (int s = 128; s > 0; s >>= 1) { if (t < s) red[t] = fmaxf(red[t], red[t + s]); __syncthreads(); }
    mx = red[0]; __syncthreads();

    float sum = 0.f;
    #pragma unroll
    for (int r = 0; r < 8; r++) { lv[r] = __expf(lv[r] - mx); sum += lv[r]; }
    red[t] = sum; __syncthreads();
    for (int s = 128; s > 0; s >>= 1) { if (t < s) red[t] += red[t + s]; __syncthreads(); }
    float inv = 1.f / red[0];

    #pragma unroll
    for (int r = 0; r < 8; r++) out[(t + r * 256) * NN + ncol] = lv[r] * inv;
}

// ---------------- launch ----------------
extern "C" void kernel_launch(void* const* d_in, const int* in_sizes, int n_in,
                              void* d_out, int out_size)
{
    const float* x         = (const float*)d_in[0];
    const float* edge_attr = (const float*)d_in[1];
    const float* user_s    = (const float*)d_in[2];
    const float* W_msg     = (const float*)d_in[3];
    const float* b_msg     = (const float*)d_in[4];
    const float* W_edge    = (const float*)d_in[5];
    const float* b_edge    = (const float*)d_in[6];
    const float* W_self    = (const float*)d_in[7];
    const float* b_self    = (const float*)d_in[8];
    const float* W1        = (const float*)d_in[9];
    const float* b1        = (const float*)d_in[10];
    const float* W2        = (const float*)d_in[11];
    const float* b2        = (const float*)d_in[12];
    const float* W3        = (const float*)d_in[13];
    const float* b3        = (const float*)d_in[14];
    const float* W4        = (const float*)d_in[15];
    const float* b4        = (const float*)d_in[16];
    const int*   edge_index = (const int*)d_in[17];
    float* out = (float*)d_out;

    __half *states, *h1, *h2, *w2h, *w3h, *w4h;
    float *h1p, *lp, *logits;
    cudaGetSymbolAddress((void**)&states, g_states);
    cudaGetSymbolAddress((void**)&h1p, g_h1p);
    cudaGetSymbolAddress((void**)&h1, g_h1);
    cudaGetSymbolAddress((void**)&h2, g_h2);
    cudaGetSymbolAddress((void**)&lp, g_lp);
    cudaGetSymbolAddress((void**)&logits, g_logits);
    cudaGetSymbolAddress((void**)&w2h, g_w2h);
    cudaGetSymbolAddress((void**)&w3h, g_w3h);
    cudaGetSymbolAddress((void**)&w4h, g_w4h);

    const int smem128 = 3 * (128 * 80 + HSTG_B);   // 44544
    const int smem64  = 3 * (64 * 80 + HSTG_B);    // 29184

    cudaFuncSetAttribute((const void*)hgemm<128, true, false, float>,
                         cudaFuncAttributeMaxDynamicSharedMemorySize, smem128);
    cudaFuncSetAttribute((const void*)hgemm<64, false, true, __half>,
                         cudaFuncAttributeMaxDynamicSharedMemorySize, smem64);
    cudaFuncSetAttribute((const void*)hgemm<64, true, false, float>,
                         cudaFuncAttributeMaxDynamicSharedMemorySize, smem64);

    cvth<<<SDIM * HID / 1024, 256>>>(W2, w2h);
    cvth<<<HID * HID2 / 1024, 256>>>(W3, w3h);
    cvth<<<HID2 * NN / 1024, 256>>>(W4, w4h);

    graph_kernel<<<BB, 256>>>(x, edge_attr, user_s, W_msg, b_msg, W_edge, b_edge,
                              W_self, b_self, W1, b1, edge_index);

    hgemm<128, true, false, float><<<dim3(HID / 64, BB / 128, 2), 256, smem128>>>(
        states, w2h, b2, h1p, BB, HID, KSPL, SDIM);
    reduce_relu<<<BB * HID / 4 / 256, 256>>>(h1p, b2, h1);

    hgemm<64, false, true, __half><<<dim3(HID2 / 64, BB / 64), 256, smem64>>>(
        h1, w3h, b3, h2, BB, HID2, HID, HID);

    hgemm<64, true, false, float><<<dim3(NN / 64, BB / 64, 2), 256, smem64>>>(
        h2, w4h, b4, lp, BB, NN, KSPL3, HID2);
    reduce_logits<<<BB * NN / 4 / 256, 256>>>(lp, b4, logits);

    softmax_kernel<<<NN, 256>>>(logits, out);
}

// round 13
// speedup vs baseline: 4.4201x; 1.1741x over previous
#include <cuda_runtime.h>
#include <cuda_fp16.h>

#define BB 2048
#define NN 64
#define EPG 512
#define TOTAL_N (BB*NN)      // 131072
#define TOTAL_E (BB*EPG)     // 1048576
#define DN 16
#define DE 64
#define DU 32
#define DUE 64
#define HID 512
#define HID2 256
#define SDIM (NN*DE + DUE)   // 4160
#define KSPL 2080            // GEMM1 split-K half
#define KSPL3 128            // GEMM3 split-K half

// ---------------- scratch (no allocs allowed) ----------------
__device__ __half g_states[BB*SDIM];
__device__ float  g_h1p[2*BB*HID];
__device__ __half g_h1[BB*HID];
__device__ __half g_h2[BB*HID2];
__device__ float  g_lp[2*BB*NN];
__device__ __half g_w2h[SDIM*HID];
__device__ __half g_w3h[HID*HID2];
__device__ __half g_w4h[HID2*NN];

// ---------------- helpers ----------------
__device__ __forceinline__ unsigned s2u(const void* p) {
    return (unsigned)__cvta_generic_to_shared(p);
}

// one kernel converts all three weight matrices (float4 granules)
#define N2Q (SDIM*HID/4)
#define N3Q (HID*HID2/4)
#define N4Q (HID2*NN/4)
__global__ __launch_bounds__(256) void cvth_all(
    const float* __restrict__ W2, const float* __restrict__ W3, const float* __restrict__ W4)
{
    int i = blockIdx.x * 256 + threadIdx.x;
    const float* s; __half* d; int j;
    if (i < N2Q)              { s = W2; d = g_w2h; j = i; }
    else if (i < N2Q + N3Q)   { s = W3; d = g_w3h; j = i - N2Q; }
    else                      { s = W4; d = g_w4h; j = i - N2Q - N3Q; }
    float4 v = ((const float4*)s)[j];
    ((__half2*)d)[2 * j]     = __floats2half2_rn(v.x, v.y);
    ((__half2*)d)[2 * j + 1] = __floats2half2_rn(v.z, v.w);
}

// ---------------- threefry2x32 (JAX, key = PRNGKey(42) = {0,42}) ----------------
__device__ __forceinline__ unsigned int rotl32(unsigned int v, int d) {
    return __funnelshift_l(v, v, d);
}

__device__ __forceinline__ unsigned int threefry_xor(unsigned int x0, unsigned int x1) {
    const unsigned int K0 = 0u, K1 = 42u;
    const unsigned int K2c = 0x1BD11BDAu ^ K0 ^ K1;
#define TF_ROUND(r) { x0 += x1; x1 = rotl32(x1, r); x1 ^= x0; }
    x0 += K0; x1 += K1;
    TF_ROUND(13) TF_ROUND(15) TF_ROUND(26) TF_ROUND(6)
    x0 += K1;  x1 += K2c + 1u;
    TF_ROUND(17) TF_ROUND(29) TF_ROUND(16) TF_ROUND(24)
    x0 += K2c; x1 += K0 + 2u;
    TF_ROUND(13) TF_ROUND(15) TF_ROUND(26) TF_ROUND(6)
    x0 += K0;  x1 += K1 + 3u;
    TF_ROUND(17) TF_ROUND(29) TF_ROUND(16) TF_ROUND(24)
    x0 += K1;  x1 += K2c + 4u;
    TF_ROUND(13) TF_ROUND(15) TF_ROUND(26) TF_ROUND(6)
    x0 += K2c; x1 += K0 + 5u;
#undef TF_ROUND
    return x0 ^ x1;
}

// ---------------- per-graph GNN kernel ----------------
__global__ __launch_bounds__(256) void graph_kernel(
    const float* __restrict__ x, const float* __restrict__ edge_attr,
    const float* __restrict__ user_s,
    const float* __restrict__ W_msg, const float* __restrict__ b_msg,
    const float* __restrict__ W_edge, const float* __restrict__ b_edge,
    const float* __restrict__ W_self, const float* __restrict__ b_self,
    const float* __restrict__ W1, const float* __restrict__ b1,
    const int* __restrict__ edge_index)
{
    __shared__ float sWm[DN][DE];                   // 4 KB
    __shared__ float sWs[DN][DE];                   // 4 KB
    __shared__ float sWe[2][DE];
    __shared__ float sbme[DE];
    __shared__ float sbs[DE];
    __shared__ __align__(16) float sx[NN][20];      // 5 KB, conflict-free gather
    __shared__ __align__(16) float sxa[NN][20];     // 5 KB
    __shared__ float2 sead[EPG];                    // 4 KB staged edge_attr
    __shared__ float2 sea2[NN];                     // per-node edge-attr sums
    __shared__ unsigned short slist[NN * 32];       // padded lists: (e<<6)|src
    __shared__ int sdeg[NN];

    const int b = blockIdx.x;
    const int t = threadIdx.x;

    for (int i = t; i < DN * DE; i += 256) {
        sWm[i / DE][i % DE] = W_msg[i];
        sWs[i / DE][i % DE] = W_self[i];
    }
    for (int i = t; i < 2 * DE; i += 256) sWe[i / DE][i % DE] = W_edge[i];
    if (t < DE) { sbme[t] = b_msg[t] + b_edge[t]; sbs[t] = b_self[t]; }
    for (int i = t; i < NN * DN; i += 256) sx[i / DN][i % DN] = x[b * NN * DN + i];
    if (t < NN) sdeg[t] = 0;
    __syncthreads();

    const int n = t >> 2;
    const int q = t & 3;

    // pass 1: one atomic per edge; slot index = returned count
    {
        const int ebase = b * EPG;
        for (int e = t; e < EPG; e += 256) {
            int src = edge_index[ebase + e] - b * NN;
            int dst = edge_index[TOTAL_E + ebase + e] - b * NN;
            int slot = atomicAdd(&sdeg[dst], 1);
            slist[(dst << 5) + slot] = (unsigned short)((e << 6) | src);
            sead[e] = ((const float2*)edge_attr)[ebase + e];
        }
    }
    __syncthreads();

    // gather: sum raw x over neighbors + edge attrs
    {
        float e0 = 0.f, e1 = 0.f;
        float4 xa = make_float4(0.f, 0.f, 0.f, 0.f);
        const int cnt = sdeg[n];
        const int lbase = n << 5;
        for (int i = 0; i < cnt; i++) {
            unsigned v = slist[lbase + i];
            int s = v & 63;
            float4 xv = *(const float4*)&sx[s][q * 4];
            xa.x += xv.x; xa.y += xv.y; xa.z += xv.z; xa.w += xv.w;
            float2 ea = sead[v >> 6];
            e0 += ea.x; e1 += ea.y;
        }
        *(float4*)&sxa[n][q * 4] = xa;
        if (q == 0) sea2[n] = make_float2(e0, e1);
    }
    __syncthreads();

    // epilogue, d-major: thread owns dim d for 16 nodes; weights in registers,
    // x reads are warp-uniform broadcasts.
    {
        const int d = t & 63, grp = t >> 6;
        float ws[DN], wm[DN];
        #pragma unroll
        for (int k = 0; k < DN; k++) { ws[k] = sWs[k][d]; wm[k] = sWm[k][d]; }
        const float we0 = sWe[0][d], we1 = sWe[1][d];
        const float bme = sbme[d],   bsv = sbs[d];

        unsigned mbits = 0;
        {
            unsigned base_idx = ((unsigned)(b * NN + grp * 16) << 6) + d;
            #pragma unroll 1
            for (int j = 0; j < 16; j++)
                mbits |= (((~threefry_xor(0u, base_idx + (j << 6))) >> 31) & 1u) << j;
        }

        #pragma unroll 4
        for (int j = 0; j < 16; j++) {
            const int n2 = grp * 16 + j;
            float4 x0 = *(const float4*)&sx[n2][0];
            float4 x1 = *(const float4*)&sx[n2][4];
            float4 x2 = *(const float4*)&sx[n2][8];
            float4 x3 = *(const float4*)&sx[n2][12];
            float4 a0 = *(const float4*)&sxa[n2][0];
            float4 a1 = *(const float4*)&sxa[n2][4];
            float4 a2 = *(const float4*)&sxa[n2][8];
            float4 a3 = *(const float4*)&sxa[n2][12];
            float acc = bsv;
            acc += x0.x*ws[0] + x0.y*ws[1] + x0.z*ws[2] + x0.w*ws[3];
            acc += x1.x*ws[4] + x1.y*ws[5] + x1.z*ws[6] + x1.w*ws[7];
            acc += x2.x*ws[8] + x2.y*ws[9] + x2.z*ws[10]+ x2.w*ws[11];
            acc += x3.x*ws[12]+ x3.y*ws[13]+ x3.z*ws[14]+ x3.w*ws[15];
            acc += a0.x*wm[0] + a0.y*wm[1] + a0.z*wm[2] + a0.w*wm[3];
            acc += a1.x*wm[4] + a1.y*wm[5] + a1.z*wm[6] + a1.w*wm[7];
            acc += a2.x*wm[8] + a2.y*wm[9] + a2.z*wm[10]+ a2.w*wm[11];
            acc += a3.x*wm[12]+ a3.y*wm[13]+ a3.z*wm[14]+ a3.w*wm[15];
            float2 ea = sea2[n2];
            float deg = (float)sdeg[n2];
            float u = acc + ea.x * we0 + ea.y * we1 + deg * bme;
            u = (u > 0.f) ? u * 2.f : 0.f;
            if (!((mbits >> j) & 1u)) u = 0.f;
            g_states[b * SDIM + n2 * DE + d] = __float2half_rn(u);
        }
    }

    // user embedding
    if (t < DUE) {
        float acc = b1[t];
        #pragma unroll
        for (int k = 0; k < DU; k++) acc += user_s[b * DU + k] * W1[k * DUE + t];
        g_states[b * SDIM + NN * DE + t] = __float2half_rn(fmaxf(acc, 0.f));
    }
}

// ---------------- fp16 tensor-core GEMM, cp.async 3-stage pipeline ----------------
__device__ __forceinline__ void mma_f16(float* d, const uint4& a, unsigned b0, unsigned b1) {
    asm volatile(
        "mma.sync.aligned.m16n8k16.row.col.f32.f16.f16.f32 "
        "{%0,%1,%2,%3}, {%4,%5,%6,%7}, {%8,%9}, {%0,%1,%2,%3};"
        : "+f"(d[0]), "+f"(d[1]), "+f"(d[2]), "+f"(d[3])
        : "r"(a.x), "r"(a.y), "r"(a.z), "r"(a.w), "r"(b0), "r"(b1));
}
__device__ __forceinline__ void ldsm4(uint4& r, unsigned addr) {
    asm volatile("ldmatrix.sync.aligned.m8n8.x4.shared.b16 {%0,%1,%2,%3}, [%4];"
                 : "=r"(r.x), "=r"(r.y), "=r"(r.z), "=r"(r.w) : "r"(addr));
}
__device__ __forceinline__ void ldsm4t(uint4& r, unsigned addr) {
    asm volatile("ldmatrix.sync.aligned.m8n8.x4.trans.shared.b16 {%0,%1,%2,%3}, [%4];"
                 : "=r"(r.x), "=r"(r.y), "=r"(r.z), "=r"(r.w) : "r"(addr));
}
#define CPA16(dst, src) asm volatile("cp.async.cg.shared.global [%0], [%1], 16;" :: "r"(dst), "l"(src))
#define CPA_COMMIT()    asm volatile("cp.async.commit_group;" ::: "memory")
#define CPA_WAIT1()     asm volatile("cp.async.wait_group 1;" ::: "memory")

#define HSTG_B 4608

template <int BMT, bool PARTIAL, bool RELU, typename OutT>
__global__ __launch_bounds__(256) void hgemm(
    const __half* __restrict__ A, const __half* __restrict__ Bw,
    const float* __restrict__ bias, OutT* __restrict__ C,
    int M, int N, int K, int lda)
{
    constexpr int WN_CNT = (BMT == 64) ? 4 : 2;
    constexpr int NWID   = 64 / WN_CNT;
    constexpr int NT     = NWID / 8;
    constexpr int AG     = BMT / 64;
    constexpr int STG_A  = BMT * 80;

    extern __shared__ char smem[];
    const unsigned sAu = s2u(smem);
    const unsigned sBu = sAu + 3 * STG_A;

    if (PARTIAL) {
        A  += (size_t)blockIdx.z * K;
        Bw += (size_t)blockIdx.z * K * N;
        C  += (size_t)blockIdx.z * M * N;
    }

    const int t = threadIdx.x, lane = t & 31, wid = t >> 5;
    const int wm = wid / WN_CNT, wn = wid % WN_CNT;
    const int m0 = blockIdx.y * BMT, n0 = blockIdx.x * 64;

    const int ar = t >> 2, agc = t & 3;
    const int br = t >> 3, bg = t & 7;

    int aoff[2];
    #pragma unroll
    for (int mt = 0; mt < 2; mt++) {
        int row = wm * 32 + mt * 16 + (lane & 7) + (((lane >> 3) & 1) << 3);
        aoff[mt] = row * 80 + (((lane >> 4) & 1) << 4);
    }
    int boff[NT / 2];
    #pragma unroll
    for (int n2 = 0; n2 < NT / 2; n2++) {
        int krow = (lane & 7) + (((lane >> 3) & 1) << 3);
        int ncol = wn * NWID + n2 * 16 + (((lane >> 4) & 1) << 3);
        boff[n2] = krow * 144 + ncol * 2;
    }

    float acc[2][NT][4];
    #pragma unroll
    for (int i = 0; i < 2; i++)
        #pragma unroll
        for (int j = 0; j < NT; j++)
            #pragma unroll
            for (int k = 0; k < 4; k++) acc[i][j][k] = 0.f;

    const int nIter = K >> 5;

    #define ISSUE(st, k0)                                                         \
    {                                                                             \
        _Pragma("unroll")                                                         \
        for (int j = 0; j < AG; j++) {                                            \
            int r = ar + 64 * j;                                                  \
            unsigned d = sAu + (st) * STG_A + r * 80 + (agc << 4);                \
            CPA16(d, A + (size_t)(m0 + r) * lda + (k0) + (agc << 3));             \
        }                                                                         \
        {                                                                         \
            unsigned d = sBu + (st) * HSTG_B + br * 144 + (bg << 4);              \
            CPA16(d, Bw + (size_t)((k0) + br) * N + n0 + (bg << 3));              \
        }                                                                         \
    }

    ISSUE(0, 0); CPA_COMMIT();
    ISSUE(1, 32); CPA_COMMIT();

    for (int it = 0; it < nIter; it++) {
        const int st = it % 3;
        CPA_WAIT1();
        __syncthreads();

        const unsigned aBase = sAu + st * STG_A;
        const unsigned bBase = sBu + st * HSTG_B;

        #pragma unroll
        for (int ks = 0; ks < 2; ks++) {
            uint4 af[2];
            #pragma unroll
            for (int mt = 0; mt < 2; mt++)
                ldsm4(af[mt], aBase + aoff[mt] + (ks << 5));
            uint4 bf[NT / 2];
            #pragma unroll
            for (int n2 = 0; n2 < NT / 2; n2++)
                ldsm4t(bf[n2], bBase + ks * 2304 + boff[n2]);
            #pragma unroll
            for (int mt = 0; mt < 2; mt++)
                #pragma unroll
                for (int nt = 0; nt < NT; nt++) {
                    unsigned bb0 = (nt & 1) ? bf[nt >> 1].z : bf[nt >> 1].x;
                    unsigned bb1 = (nt & 1) ? bf[nt >> 1].w : bf[nt >> 1].y;
                    mma_f16(acc[mt][nt], af[mt], bb0, bb1);
                }
        }

        if (it + 2 < nIter) { const int ns = (it + 2) % 3; ISSUE(ns, (it + 2) << 5); }
        CPA_COMMIT();
    }
    #undef ISSUE

    #pragma unroll
    for (int mt = 0; mt < 2; mt++) {
        int r0 = m0 + wm * 32 + mt * 16 + (lane >> 2);
        #pragma unroll
        for (int nt = 0; nt < NT; nt++) {
            int c = n0 + wn * NWID + nt * 8 + ((lane & 3) << 1);
            float v0 = acc[mt][nt][0];
            float v1 = acc[mt][nt][1];
            float v2 = acc[mt][nt][2];
            float v3 = acc[mt][nt][3];
            if (PARTIAL) {
                *(float2*)&((float*)C)[(size_t)r0 * N + c]       = make_float2(v0, v1);
                *(float2*)&((float*)C)[(size_t)(r0 + 8) * N + c] = make_float2(v2, v3);
            } else {
                float bv0 = bias[c], bv1 = bias[c + 1];
                v0 += bv0; v1 += bv1; v2 += bv0; v3 += bv1;
                if (RELU) {
                    v0 = fmaxf(v0, 0.f); v1 = fmaxf(v1, 0.f);
                    v2 = fmaxf(v2, 0.f); v3 = fmaxf(v3, 0.f);
                }
                if (sizeof(OutT) == 2) {
                    *(__half2*)&((__half*)C)[(size_t)r0 * N + c]       = __floats2half2_rn(v0, v1);
                    *(__half2*)&((__half*)C)[(size_t)(r0 + 8) * N + c] = __floats2half2_rn(v2, v3);
                } else {
                    *(float2*)&((float*)C)[(size_t)r0 * N + c]       = make_float2(v0, v1);
                    *(float2*)&((float*)C)[(size_t)(r0 + 8) * N + c] = make_float2(v2, v3);
                }
            }
        }
    }
}

// ---------------- split-K reduce + bias + relu -> fp16 h1 ----------------
__global__ __launch_bounds__(256) void reduce_relu(
    const float* __restrict__ p, const float* __restrict__ bias, __half* __restrict__ o)
{
    int i = blockIdx.x * 256 + threadIdx.x;
    float4 a = ((const float4*)p)[i];
    float4 b = ((const float4*)p)[i + (BB * HID / 4)];
    int c = (i * 4) & (HID - 1);
    float4 bv = *(const float4*)&bias[c];
    __half2 r0 = __floats2half2_rn(fmaxf(a.x + b.x + bv.x, 0.f), fmaxf(a.y + b.y + bv.y, 0.f));
    __half2 r1 = __floats2half2_rn(fmaxf(a.z + b.z + bv.z, 0.f), fmaxf(a.w + b.w + bv.w, 0.f));
    ((__half2*)o)[2 * i]     = r0;
    ((__half2*)o)[2 * i + 1] = r1;
}

// ---------------- softmax over BATCH axis, fused logits split-K reduce ----------
__global__ __launch_bounds__(256) void softmax_kernel(
    const float* __restrict__ lp, const float* __restrict__ b4, float* __restrict__ out)
{
    const int ncol = blockIdx.x;
    const int t = threadIdx.x;
    __shared__ float red[256];

    const float bv = b4[ncol];
    float lv[8];
    #pragma unroll
    for (int r = 0; r < 8; r++) {
        int idx = (t + r * 256) * NN + ncol;
        lv[r] = lp[idx] + lp[BB * NN + idx] + bv;
    }

    float mx = lv[0];
    #pragma unroll
    for (int r = 1; r < 8; r++) mx = fmaxf(mx, lv[r]);
    red[t] = mx; __syncthreads();
    for (int s = 128; s > 0; s >>= 1) { if (t < s) red[t] = fmaxf(red[t], red[t + s]); __syncthreads(); }
    mx = red[0]; __syncthreads();

    float sum = 0.f;
    #pragma unroll
    for (int r = 0; r < 8; r++) { lv[r] = __expf(lv[r] - mx); sum += lv[r]; }
    red[t] = sum; __syncthreads();
    for (int s = 128; s > 0; s >>= 1) { if (t < s) red[t] += red[t + s]; __syncthreads(); }
    float inv = 1.f / red[0];

    #pragma unroll
    for (int r = 0; r < 8; r++) out[(t + r * 256) * NN + ncol] = lv[r] * inv;
}

// ---------------- launch ----------------
extern "C" void kernel_launch(void* const* d_in, const int* in_sizes, int n_in,
                              void* d_out, int out_size)
{
    const float* x         = (const float*)d_in[0];
    const float* edge_attr = (const float*)d_in[1];
    const float* user_s    = (const float*)d_in[2];
    const float* W_msg     = (const float*)d_in[3];
    const float* b_msg     = (const float*)d_in[4];
    const float* W_edge    = (const float*)d_in[5];
    const float* b_edge    = (const float*)d_in[6];
    const float* W_self    = (const float*)d_in[7];
    const float* b_self    = (const float*)d_in[8];
    const float* W1        = (const float*)d_in[9];
    const float* b1        = (const float*)d_in[10];
    const float* W2        = (const float*)d_in[11];
    const float* b2        = (const float*)d_in[12];
    const float* W3        = (const float*)d_in[13];
    const float* b3        = (const float*)d_in[14];
    const float* W4        = (const float*)d_in[15];
    const float* b4        = (const float*)d_in[16];
    const int*   edge_index = (const int*)d_in[17];
    float* out = (float*)d_out;

    __half *states, *h1, *h2, *w2h, *w3h, *w4h;
    float *h1p, *lp;
    cudaGetSymbolAddress((void**)&states, g_states);
    cudaGetSymbolAddress((void**)&h1p, g_h1p);
    cudaGetSymbolAddress((void**)&h1, g_h1);
    cudaGetSymbolAddress((void**)&h2, g_h2);
    cudaGetSymbolAddress((void**)&lp, g_lp);
    cudaGetSymbolAddress((void**)&w2h, g_w2h);
    cudaGetSymbolAddress((void**)&w3h, g_w3h);
    cudaGetSymbolAddress((void**)&w4h, g_w4h);

    const int smem128 = 3 * (128 * 80 + HSTG_B);   // 44544
    const int smem64  = 3 * (64 * 80 + HSTG_B);    // 29184

    cudaFuncSetAttribute((const void*)hgemm<128, true, false, float>,
                         cudaFuncAttributeMaxDynamicSharedMemorySize, smem128);
    cudaFuncSetAttribute((const void*)hgemm<64, false, true, __half>,
                         cudaFuncAttributeMaxDynamicSharedMemorySize, smem64);
    cudaFuncSetAttribute((const void*)hgemm<64, true, false, float>,
                         cudaFuncAttributeMaxDynamicSharedMemorySize, smem64);

    cvth_all<<<(N2Q + N3Q + N4Q + 255) / 256, 256>>>(W2, W3, W4);

    graph_kernel<<<BB, 256>>>(x, edge_attr, user_s, W_msg, b_msg, W_edge, b_edge,
                              W_self, b_self, W1, b1, edge_index);

    hgemm<128, true, false, float><<<dim3(HID / 64, BB / 128, 2), 256, smem128>>>(
        states, w2h, b2, h1p, BB, HID, KSPL, SDIM);
    reduce_relu<<<BB * HID / 4 / 256, 256>>>(h1p, b2, h1);

    hgemm<64, false, true, __half><<<dim3(HID2 / 64, BB / 64), 256, smem64>>>(
        h1, w3h, b3, h2, BB, HID2, HID, HID);

    hgemm<64, true, false, float><<<dim3(NN / 64, BB / 64, 2), 256, smem64>>>(
        h2, w4h, b4, lp, BB, NN, KSPL3, HID2);

    softmax_kernel<<<NN, 256>>>(lp, b4, out);
}